// round 12
// baseline (speedup 1.0000x reference)
#include <cuda_runtime.h>
#include <cuda_fp16.h>
#include <cstdint>

#define LATENT   128
#define HIDDEN   256
#define NTYPES   32
#define ETYPES   8
#define E_TILE   128
#define THREADS  256
#define ASTRIDE  264          // fp16 elems per A row (pad: conflict-free ldmatrix)
#define CHUNK_S  2            // k16-steps per B chunk
#define NCHK     8

// dynamic smem layout (bytes):
//  A: 128*264*2 = 67584     @0   (partial overlay 8 x 64 x 8 f32 = 16384 after mainloop)
//  Bbuf0: 16384             @67584
//  Bbuf1: 16384             @83968
#define SM_B0     67584
#define SM_BBYTES 16384
#define DSMEM_BYTES (67584 + 2 * 16384)

// fragment-ready packed W1 fp16 (GEMM1 B operand)
__device__ unsigned int g_B[32768];
// fragment-ready W2 fp16 hi/lo (GEMM2 B operand): idx = ((kstep*32+lane)*2 + q)
__device__ unsigned int g_B2h[1024];
__device__ unsigned int g_B2l[1024];

__device__ __forceinline__ unsigned int smem_u32(const void* p) {
    unsigned int a;
    asm("{ .reg .u64 t; cvta.to.shared.u64 t, %1; cvt.u32.u64 %0, t; }" : "=r"(a) : "l"(p));
    return a;
}
__device__ __forceinline__ unsigned int pack_h2(__half a, __half b) {
    __half2 h = __halves2half2(a, b);
    return *reinterpret_cast<unsigned int*>(&h);
}
__device__ __forceinline__ void mma_f16(float* c, const unsigned int* a,
                                        unsigned int b0, unsigned int b1) {
    asm volatile(
        "mma.sync.aligned.m16n8k16.row.col.f32.f16.f16.f32 "
        "{%0,%1,%2,%3}, {%4,%5,%6,%7}, {%8,%9}, {%0,%1,%2,%3};"
        : "+f"(c[0]), "+f"(c[1]), "+f"(c[2]), "+f"(c[3])
        : "r"(a[0]), "r"(a[1]), "r"(a[2]), "r"(a[3]), "r"(b0), "r"(b1));
}
__device__ __forceinline__ void ldmatrix4(unsigned int* r, unsigned int addr) {
    asm volatile("ldmatrix.sync.aligned.m8n8.x4.shared.b16 {%0,%1,%2,%3}, [%4];"
                 : "=r"(r[0]), "=r"(r[1]), "=r"(r[2]), "=r"(r[3]) : "r"(addr));
}
__device__ __forceinline__ void cp_async16(unsigned int dst, const void* src) {
    asm volatile("cp.async.cg.shared.global [%0], [%1], 16;" :: "r"(dst), "l"(src));
}
__device__ __forceinline__ void cp_commit() {
    asm volatile("cp.async.commit_group;" ::: "memory");
}
__device__ __forceinline__ void cp_wait0() {
    asm volatile("cp.async.wait_group 0;" ::: "memory");
}

// ---------------- prep: pack W1 into fragment-ready fp16 ----------------
__global__ void prep_w1(const float* __restrict__ W1) {
    int p = blockIdx.x * 256 + threadIdx.x;
    int l = p & 31;
    int T = (p >> 5) & 31;
    int s = p >> 10;
    int n  = T * 8 + (l >> 2);
    int kb = s * 16 + 2 * (l & 3);
#pragma unroll
    for (int q = 0; q < 2; q++) {
        int k = kb + q * 8;
        __half h0 = __float2half_rn(W1[k * HIDDEN + n]);
        __half h1 = __float2half_rn(W1[(k + 1) * HIDDEN + n]);
        g_B[p * 2 + q] = pack_h2(h0, h1);
    }
}

// ---------------- prep: pack W2 into fragment-ready fp16 hi/lo ----------------
__global__ void prep_w2(const float* __restrict__ W2) {
    int p = blockIdx.x * 256 + threadIdx.x;   // 0..511
    if (p >= 512) return;
    int lane = p & 31;
    int kstep = p >> 5;                       // 0..15
    int g   = lane >> 2;
    int tig = lane & 3;
    int k0  = kstep * 16 + 2 * tig;
#pragma unroll
    for (int q = 0; q < 2; q++) {
        int k = k0 + q * 8;
        float v0 = W2[k * ETYPES + g];
        float v1 = W2[(k + 1) * ETYPES + g];
        __half h0 = __float2half_rn(v0);
        __half h1 = __float2half_rn(v1);
        g_B2h[p * 2 + q] = pack_h2(h0, h1);
        g_B2l[p * 2 + q] = pack_h2(__float2half_rn(v0 - __half2float(h0)),
                                   __float2half_rn(v1 - __half2float(h1)));
    }
}

// ---------------- node logits ----------------
__global__ void node_kernel(const float* __restrict__ z,
                            const float* __restrict__ Wn,
                            const float* __restrict__ bn,
                            float* __restrict__ out, int n_nodes) {
    __shared__ float ws[LATENT * NTYPES];
    __shared__ float zs[32 * 132];
    __shared__ float bs[NTYPES];
    int tid = threadIdx.x;
    for (int idx = tid; idx < LATENT * NTYPES / 4; idx += THREADS)
        ((float4*)ws)[idx] = ((const float4*)Wn)[idx];
    if (tid < NTYPES) bs[tid] = bn[tid];
    long long nBase = (long long)blockIdx.x * 32;
    for (int idx = tid; idx < 32 * LATENT / 4; idx += THREADS) {
        int n = idx / (LATENT / 4), kk = idx % (LATENT / 4);
        long long gn = nBase + n;
        float4 v = make_float4(0.f, 0.f, 0.f, 0.f);
        if (gn < n_nodes) v = *(const float4*)(z + gn * LATENT + kk * 4);
        *(float4*)(zs + n * 132 + kk * 4) = v;
    }
    __syncthreads();
    int n = tid >> 3, tg = tid & 7;
    float a0 = bs[tg*4+0], a1 = bs[tg*4+1], a2 = bs[tg*4+2], a3 = bs[tg*4+3];
    const float* zr = zs + n * 132;
#pragma unroll 8
    for (int k = 0; k < LATENT; k++) {
        float zv = zr[k];
        float4 w = *(const float4*)(ws + k * NTYPES + tg * 4);
        a0 = fmaf(zv, w.x, a0); a1 = fmaf(zv, w.y, a1);
        a2 = fmaf(zv, w.z, a2); a3 = fmaf(zv, w.w, a3);
    }
    long long gn = nBase + n;
    if (gn < n_nodes)
        *(float4*)(out + gn * NTYPES + tg * 4) = make_float4(a0, a1, a2, a3);
}

// ---------------- edge kernel: 128-edge tiles, 2m x 4n warps, fused GEMM2 ----
// warp (mh = warp>>2, nq = warp&3): m64 (rows mh*64+) x n64 (cols nq*64+)
__global__ void __launch_bounds__(THREADS, 1)
edge_kernel(const float* __restrict__ z,
            const int* __restrict__ ei,
            const float* __restrict__ b1,
            const float* __restrict__ b2,
            float* __restrict__ out,
            int n_edges, int n_nodes) {
    extern __shared__ char dsm[];
    __shared__ int   idx_r[E_TILE];
    __shared__ int   idx_c[E_TILE];
    __shared__ float b1s[HIDDEN];
    __shared__ float b2s[ETYPES];

    int tid  = threadIdx.x;
    int lane = tid & 31;
    int warp = tid >> 5;
    int mh   = warp >> 2;
    int nq   = warp & 3;
    long long eBase = (long long)blockIdx.x * E_TILE;

    unsigned int smb = smem_u32(dsm);

    // ---- prefetch B chunk 0
    {
        unsigned int dst = smb + SM_B0;
        const uint4* sb = (const uint4*)g_B;
#pragma unroll
        for (int u = 0; u < 4; u++)
            cp_async16(dst + (tid + u * THREADS) * 16, sb + tid + u * THREADS);
        cp_commit();
    }

    // ---- stage b1 / b2 / edge indices
    if (tid < HIDDEN) b1s[tid] = b1[tid];
    if (tid < ETYPES) b2s[tid] = b2[tid];
    if (tid < E_TILE) {
        long long e = eBase + tid;
        if (e >= n_edges) e = n_edges - 1;
        int r = ei[e];
        int c = ei[(long long)n_edges + e];
        idx_r[tid] = min(max(r, 0), n_nodes - 1);
        idx_c[tid] = min(max(c, 0), n_nodes - 1);
    }
    __syncthreads();

    // ---- gather A: 128 edges x 256 k, fp16; thread -> 1 edge half (128 k)
    {
        int e_loc = tid >> 1;
        int half  = tid & 1;
        int node  = half ? idx_c[e_loc] : idx_r[e_loc];
        const float* src = z + (long long)node * LATENT;
        unsigned short* Ah = (unsigned short*)dsm;
        int base = e_loc * ASTRIDE + half * 128;
#pragma unroll
        for (int g = 0; g < 32; g++) {
            float4 v = *(const float4*)(src + g * 4);
            uint2 pk;
            pk.x = pack_h2(__float2half_rn(v.x), __float2half_rn(v.y));
            pk.y = pack_h2(__float2half_rn(v.z), __float2half_rn(v.w));
            *(uint2*)(Ah + base + g * 4) = pk;
        }
    }

    // ---- mainloop (GEMM1): warp m64 x n64
    float acc[4][8][4];
#pragma unroll
    for (int i = 0; i < 4; i++)
#pragma unroll
        for (int t = 0; t < 8; t++)
#pragma unroll
            for (int r = 0; r < 4; r++) acc[i][t][r] = 0.f;

    unsigned int a_row = (unsigned)(lane & 15);
    unsigned int a_col = (unsigned)((lane >> 4) * 8);

    for (int c = 0; c < NCHK; c++) {
        cp_wait0();
        __syncthreads();
        if (c + 1 < NCHK) {
            unsigned int dst = smb + SM_B0 + ((c + 1) & 1) * SM_BBYTES;
            const uint4* sb = (const uint4*)(g_B + (c + 1) * 4096);
#pragma unroll
            for (int u = 0; u < 4; u++)
                cp_async16(dst + (tid + u * THREADS) * 16, sb + tid + u * THREADS);
            cp_commit();
        }

        unsigned int bbase = smb + SM_B0 + (c & 1) * SM_BBYTES;
#pragma unroll
        for (int s = 0; s < CHUNK_S; s++) {
            int k0 = (c * CHUNK_S + s) * 16;
            unsigned int bw[8][2];
#pragma unroll
            for (int t = 0; t < 8; t++) {
                int T = nq * 8 + t;
                unsigned int boff = bbase + (((unsigned)(s * 32 + T) * 32 + lane) * 8);
                asm volatile("ld.shared.v2.u32 {%0,%1}, [%2];"
                             : "=r"(bw[t][0]), "=r"(bw[t][1]) : "r"(boff));
            }
#pragma unroll
            for (int i = 0; i < 4; i++) {
                unsigned int ah[4];
                int mrow = (mh * 4 + i) * 16;
                unsigned int off = ((mrow + a_row) * ASTRIDE + k0 + a_col) * 2;
                ldmatrix4(ah, smb + off);
#pragma unroll
                for (int t = 0; t < 8; t++)
                    mma_f16(acc[i][t], ah, bw[t][0], bw[t][1]);
            }
        }
        __syncthreads();
    }

    // ---- GEMM2 in registers: warp owns h cols [nq*64, nq*64+64) -> 4 k16-steps
    int g   = lane >> 2;
    int tig = lane & 3;
    float cacc[4][4];
#pragma unroll
    for (int i = 0; i < 4; i++)
#pragma unroll
        for (int r = 0; r < 4; r++) cacc[i][r] = 0.f;

#pragma unroll
    for (int s2 = 0; s2 < 4; s2++) {
        int kstep = nq * 4 + s2;
        uint2 bh = *(const uint2*)(g_B2h + (kstep * 32 + lane) * 2);
        uint2 bl = *(const uint2*)(g_B2l + (kstep * 32 + lane) * 2);
        int cb = nq * 64 + s2 * 16 + 2 * tig;
        float f0 = b1s[cb],     f1 = b1s[cb + 1];
        float f8 = b1s[cb + 8], f9 = b1s[cb + 9];
#pragma unroll
        for (int i = 0; i < 4; i++) {
            float* cA = acc[i][2 * s2];
            float* cB = acc[i][2 * s2 + 1];
            unsigned int afr[4];
            afr[0] = pack_h2(__float2half_rn(fmaxf(cA[0] + f0, 0.f)),
                             __float2half_rn(fmaxf(cA[1] + f1, 0.f)));
            afr[1] = pack_h2(__float2half_rn(fmaxf(cA[2] + f0, 0.f)),
                             __float2half_rn(fmaxf(cA[3] + f1, 0.f)));
            afr[2] = pack_h2(__float2half_rn(fmaxf(cB[0] + f8, 0.f)),
                             __float2half_rn(fmaxf(cB[1] + f9, 0.f)));
            afr[3] = pack_h2(__float2half_rn(fmaxf(cB[2] + f8, 0.f)),
                             __float2half_rn(fmaxf(cB[3] + f9, 0.f)));
            mma_f16(cacc[i], afr, bh.x, bh.y);
            mma_f16(cacc[i], afr, bl.x, bl.y);
        }
    }

    // ---- cross-warp reduction: partials are m64 x 8 per warp
    __syncthreads();                       // A smem dead; reuse as partial buffers
    float* part = (float*)dsm;             // 8 warps x 512 floats
    float* pw = part + warp * 512;
#pragma unroll
    for (int i = 0; i < 4; i++) {
        int m0 = i * 16 + g;               // local row within warp's m64
        *(float2*)(pw + m0 * 8 + 2 * tig)       = make_float2(cacc[i][0], cacc[i][1]);
        *(float2*)(pw + (m0 + 8) * 8 + 2 * tig) = make_float2(cacc[i][2], cacc[i][3]);
    }
    __syncthreads();

    // 1024 outputs = 128 edges x 8 types; each sums partials from 4 nq-warps
#pragma unroll
    for (int rep = 0; rep < 4; rep++) {
        int idx = tid + rep * THREADS;     // 0..1023 -> (m, o)
        int m = idx >> 3, o = idx & 7;
        int mh2 = m >> 6, ml = m & 63;
        float s = b2s[o];
#pragma unroll
        for (int q = 0; q < 4; q++)
            s += part[(mh2 * 4 + q) * 512 + ml * 8 + o];
        long long ge = eBase + m;
        if (ge < n_edges) out[ge * ETYPES + o] = s;
    }
}

// ---------------- launch ----------------
extern "C" void kernel_launch(void* const* d_in, const int* in_sizes, int n_in,
                              void* d_out, int out_size) {
    const float* z  = (const float*)d_in[0];
    const int*   ei = (const int*)d_in[1];
    const float* Wn = (const float*)d_in[2];
    const float* bn = (const float*)d_in[3];
    const float* W1 = (const float*)d_in[4];
    const float* b1 = (const float*)d_in[5];
    const float* W2 = (const float*)d_in[6];
    const float* b2 = (const float*)d_in[7];

    int n_nodes = in_sizes[0] / LATENT;
    int n_edges = in_sizes[1] / 2;
    float* out = (float*)d_out;

    prep_w1<<<64, 256>>>(W1);
    prep_w2<<<2, 256>>>(W2);
    node_kernel<<<(n_nodes + 31) / 32, THREADS>>>(z, Wn, bn, out, n_nodes);

    cudaFuncSetAttribute(edge_kernel, cudaFuncAttributeMaxDynamicSharedMemorySize, DSMEM_BYTES);
    int grid = (n_edges + E_TILE - 1) / E_TILE;
    edge_kernel<<<grid, THREADS, DSMEM_BYTES>>>(
        z, ei, b1, b2, out + (size_t)n_nodes * NTYPES, n_edges, n_nodes);
}

// round 13
// speedup vs baseline: 3.1203x; 3.1203x over previous
#include <cuda_runtime.h>
#include <cuda_fp16.h>
#include <cstdint>

#define LATENT   128
#define HIDDEN   256
#define NTYPES   32
#define ETYPES   8
#define THREADS  256

// ---------- persistent device scratch ----------
// W1 fragment packs: 8 s-steps x 32 T x 32 lanes x 2 q  (U-half: k<128, V-half: k>=128)
__device__ unsigned int g_Bu[16384];
__device__ unsigned int g_Bv[16384];
// W2 fragment packs (hi/lo fp16): 16 kstep x 32 lane x 2
__device__ unsigned int g_B2h[1024];
__device__ unsigned int g_B2l[1024];
// UV table: per node 512 fp16 (U' = z*W1_top + b1 in cols 0..255, V = z*W1_bot in 256..511)
// stored as u32 (fp16x2): 50048 * 256
__device__ unsigned int g_UV[12812288];

// ---------- helpers ----------
__device__ __forceinline__ unsigned int smem_u32(const void* p) {
    unsigned int a;
    asm("{ .reg .u64 t; cvta.to.shared.u64 t, %1; cvt.u32.u64 %0, t; }" : "=r"(a) : "l"(p));
    return a;
}
__device__ __forceinline__ unsigned int pack_h2(__half a, __half b) {
    __half2 h = __halves2half2(a, b);
    return *reinterpret_cast<unsigned int*>(&h);
}
__device__ __forceinline__ unsigned int pack_f2(float a, float b) {
    return pack_h2(__float2half_rn(a), __float2half_rn(b));
}
__device__ __forceinline__ unsigned int h2_add_relu(unsigned int a, unsigned int b) {
    __half2 s = __hadd2(*reinterpret_cast<__half2*>(&a), *reinterpret_cast<__half2*>(&b));
    __half2 z = __float2half2_rn(0.f);
    s = __hmax2(s, z);
    return *reinterpret_cast<unsigned int*>(&s);
}
__device__ __forceinline__ void mma_f16(float* c, const unsigned int* a,
                                        unsigned int b0, unsigned int b1) {
    asm volatile(
        "mma.sync.aligned.m16n8k16.row.col.f32.f16.f16.f32 "
        "{%0,%1,%2,%3}, {%4,%5,%6,%7}, {%8,%9}, {%0,%1,%2,%3};"
        : "+f"(c[0]), "+f"(c[1]), "+f"(c[2]), "+f"(c[3])
        : "r"(a[0]), "r"(a[1]), "r"(a[2]), "r"(a[3]), "r"(b0), "r"(b1));
}
__device__ __forceinline__ void ldmatrix4(unsigned int* r, unsigned int addr) {
    asm volatile("ldmatrix.sync.aligned.m8n8.x4.shared.b16 {%0,%1,%2,%3}, [%4];"
                 : "=r"(r[0]), "=r"(r[1]), "=r"(r[2]), "=r"(r[3]) : "r"(addr));
}
__device__ __forceinline__ void cp_async16(unsigned int dst, const void* src) {
    asm volatile("cp.async.cg.shared.global [%0], [%1], 16;" :: "r"(dst), "l"(src));
}
__device__ __forceinline__ void cp_commit() {
    asm volatile("cp.async.commit_group;" ::: "memory");
}
__device__ __forceinline__ void cp_wait0() {
    asm volatile("cp.async.wait_group 0;" ::: "memory");
}

// ---------------- prep: pack W1 halves into fragment-ready fp16 ----------------
__global__ void prep_w1cat(const float* __restrict__ W1) {
    int p = blockIdx.x * 256 + threadIdx.x;    // 0..8191: (s<8, T<32, lane<32)
    int l = p & 31;
    int T = (p >> 5) & 31;
    int s = p >> 10;
    int n  = T * 8 + (l >> 2);
    int kb = s * 16 + 2 * (l & 3);
#pragma unroll
    for (int q = 0; q < 2; q++) {
        int k = kb + q * 8;
        g_Bu[p * 2 + q] = pack_f2(W1[k * HIDDEN + n],         W1[(k + 1) * HIDDEN + n]);
        g_Bv[p * 2 + q] = pack_f2(W1[(k + 128) * HIDDEN + n], W1[(k + 129) * HIDDEN + n]);
    }
}

// ---------------- prep: pack W2 into fragment-ready fp16 hi/lo ----------------
__global__ void prep_w2(const float* __restrict__ W2) {
    int p = blockIdx.x * 256 + threadIdx.x;   // 0..511
    if (p >= 512) return;
    int lane = p & 31;
    int g   = lane >> 2;
    int tig = lane & 3;
    int k0  = (p >> 5) * 16 + 2 * tig;
#pragma unroll
    for (int q = 0; q < 2; q++) {
        int k = k0 + q * 8;
        float v0 = W2[k * ETYPES + g];
        float v1 = W2[(k + 1) * ETYPES + g];
        __half h0 = __float2half_rn(v0);
        __half h1 = __float2half_rn(v1);
        g_B2h[p * 2 + q] = pack_h2(h0, h1);
        g_B2l[p * 2 + q] = pack_h2(__float2half_rn(v0 - __half2float(h0)),
                                   __float2half_rn(v1 - __half2float(h1)));
    }
}

// ---------------- node logits (unchanged, validated) ----------------
__global__ void node_kernel(const float* __restrict__ z,
                            const float* __restrict__ Wn,
                            const float* __restrict__ bn,
                            float* __restrict__ out, int n_nodes) {
    __shared__ float ws[LATENT * NTYPES];
    __shared__ float zs[32 * 132];
    __shared__ float bs[NTYPES];
    int tid = threadIdx.x;
    for (int idx = tid; idx < LATENT * NTYPES / 4; idx += THREADS)
        ((float4*)ws)[idx] = ((const float4*)Wn)[idx];
    if (tid < NTYPES) bs[tid] = bn[tid];
    long long nBase = (long long)blockIdx.x * 32;
    for (int idx = tid; idx < 32 * LATENT / 4; idx += THREADS) {
        int n = idx / (LATENT / 4), kk = idx % (LATENT / 4);
        long long gn = nBase + n;
        float4 v = make_float4(0.f, 0.f, 0.f, 0.f);
        if (gn < n_nodes) v = *(const float4*)(z + gn * LATENT + kk * 4);
        *(float4*)(zs + n * 132 + kk * 4) = v;
    }
    __syncthreads();
    int n = tid >> 3, tg = tid & 7;
    float a0 = bs[tg*4+0], a1 = bs[tg*4+1], a2 = bs[tg*4+2], a3 = bs[tg*4+3];
    const float* zr = zs + n * 132;
#pragma unroll 8
    for (int k = 0; k < LATENT; k++) {
        float zv = zr[k];
        float4 w = *(const float4*)(ws + k * NTYPES + tg * 4);
        a0 = fmaf(zv, w.x, a0); a1 = fmaf(zv, w.y, a1);
        a2 = fmaf(zv, w.z, a2); a3 = fmaf(zv, w.w, a3);
    }
    long long gn = nBase + n;
    if (gn < n_nodes)
        *(float4*)(out + gn * NTYPES + tg * 4) = make_float4(a0, a1, a2, a3);
}

// ---------------- uv kernel: per-node GEMM, 64 nodes x 256 cols per block ----
// blockIdx: mt = blk>>1 (node tile), p = blk&1 (0: U-half +b1, 1: V-half)
// warps: mh = warp>>2 (2 m-halves of 32), nq = warp&3 (4 n-quarters of 64)
// A: z rows 64 x 128 fp16 (stride 136); B: g_Bu/g_Bv streamed 4 chunks of 2 s-steps
#define UV_ASTR   136
#define UV_SM_B0  (64 * UV_ASTR * 2)          // 17408
#define UV_SMEM   (UV_SM_B0 + 2 * 16384)      // 50176
__global__ void __launch_bounds__(THREADS, 2)
uv_kernel(const float* __restrict__ z,
          const float* __restrict__ b1,
          int n_nodes) {
    extern __shared__ char dsm[];
    __shared__ float b1s[HIDDEN];

    int tid  = threadIdx.x;
    int lane = tid & 31;
    int warp = tid >> 5;
    int mh   = warp >> 2;
    int nq   = warp & 3;
    int p    = blockIdx.x & 1;
    long long nodeBase = (long long)(blockIdx.x >> 1) * 64;

    unsigned int smb = smem_u32(dsm);
    const unsigned int* Bsrc = p ? g_Bv : g_Bu;

    // prefetch B chunk 0 (16KB)
    {
        unsigned int dst = smb + UV_SM_B0;
        const uint4* sb = (const uint4*)Bsrc;
#pragma unroll
        for (int u = 0; u < 4; u++)
            cp_async16(dst + (tid + u * THREADS) * 16, sb + tid + u * THREADS);
        cp_commit();
    }

    if (tid < HIDDEN) b1s[tid] = b1[tid];

    // stage A: 64 nodes x 128 k fp16
    {
        int n_l = tid >> 2;
        int q   = tid & 3;
        long long node = nodeBase + n_l;
        if (node >= n_nodes) node = n_nodes - 1;
        const float* src = z + node * LATENT + q * 32;
        unsigned short* A = (unsigned short*)dsm;
        int base = n_l * UV_ASTR + q * 32;
#pragma unroll
        for (int gg = 0; gg < 4; gg++) {
            float4 a = *(const float4*)(src + gg * 8);
            float4 b = *(const float4*)(src + gg * 8 + 4);
            uint4 pk;
            pk.x = pack_f2(a.x, a.y);
            pk.y = pack_f2(a.z, a.w);
            pk.z = pack_f2(b.x, b.y);
            pk.w = pack_f2(b.z, b.w);
            *(uint4*)(A + base + gg * 8) = pk;
        }
    }

    float acc[2][8][4];
#pragma unroll
    for (int i = 0; i < 2; i++)
#pragma unroll
        for (int t = 0; t < 8; t++)
#pragma unroll
            for (int r = 0; r < 4; r++) acc[i][t][r] = 0.f;

    unsigned int a_row = (unsigned)(lane & 15);
    unsigned int a_col = (unsigned)((lane >> 4) * 8);

    for (int c = 0; c < 4; c++) {               // 4 chunks x 2 s-steps = K 128
        cp_wait0();
        __syncthreads();
        if (c + 1 < 4) {
            unsigned int dst = smb + UV_SM_B0 + ((c + 1) & 1) * 16384;
            const uint4* sb = (const uint4*)(Bsrc + (c + 1) * 4096);
#pragma unroll
            for (int u = 0; u < 4; u++)
                cp_async16(dst + (tid + u * THREADS) * 16, sb + tid + u * THREADS);
            cp_commit();
        }
        unsigned int bbase = smb + UV_SM_B0 + (c & 1) * 16384;
#pragma unroll
        for (int s = 0; s < 2; s++) {
            int k0 = (c * 2 + s) * 16;
            unsigned int bw[8][2];
#pragma unroll
            for (int t = 0; t < 8; t++) {
                int T = nq * 8 + t;
                unsigned int boff = bbase + (((unsigned)(s * 32 + T) * 32 + lane) * 8);
                asm volatile("ld.shared.v2.u32 {%0,%1}, [%2];"
                             : "=r"(bw[t][0]), "=r"(bw[t][1]) : "r"(boff));
            }
#pragma unroll
            for (int i = 0; i < 2; i++) {
                unsigned int ah[4];
                int mrow = (mh * 2 + i) * 16;
                unsigned int off = ((mrow + a_row) * UV_ASTR + k0 + a_col) * 2;
                ldmatrix4(ah, smb + off);
#pragma unroll
                for (int t = 0; t < 8; t++)
                    mma_f16(acc[i][t], ah, bw[t][0], bw[t][1]);
            }
        }
        __syncthreads();
    }

    // epilogue: (+b1 for U-half), cvt fp16, store to g_UV
    int g   = lane >> 2;
    int tig = lane & 3;
#pragma unroll
    for (int i = 0; i < 2; i++) {
#pragma unroll
        for (int t = 0; t < 8; t++) {
            int col = nq * 64 + t * 8 + 2 * tig;
            float bb0 = p ? 0.f : b1s[col];
            float bb1 = p ? 0.f : b1s[col + 1];
            long long node0 = nodeBase + (mh * 2 + i) * 16 + g;
            unsigned int h20 = pack_f2(acc[i][t][0] + bb0, acc[i][t][1] + bb1);
            unsigned int h21 = pack_f2(acc[i][t][2] + bb0, acc[i][t][3] + bb1);
            if (node0 < n_nodes)
                g_UV[node0 * 256 + p * 128 + (col >> 1)] = h20;
            if (node0 + 8 < n_nodes)
                g_UV[(node0 + 8) * 256 + p * 128 + (col >> 1)] = h21;
        }
    }
}

// ---------------- edge kernel v2: gather UV, fp16 add+relu, mma GEMM2 ----------
// warp-private: 16 edges per group; h buffer 16 x 264 fp16 per warp (8448 B)
#define EK_HSTR  264
#define EK_WBUF  (16 * EK_HSTR * 2)           // 8448
#define EK_SMEM  (8 * EK_WBUF)                // 67584
__global__ void __launch_bounds__(THREADS, 2)
edge_kernel(const int* __restrict__ ei,
            const float* __restrict__ b2,
            float* __restrict__ out,
            int n_edges, int n_nodes) {
    extern __shared__ char dsm[];
    int tid  = threadIdx.x;
    int lane = tid & 31;
    int warp = tid >> 5;

    unsigned int hbase = smem_u32(dsm) + warp * EK_WBUF;

    // preload W2 fragments (hi/lo) and b2 slice
    uint2 w2h[16], w2l[16];
#pragma unroll
    for (int s = 0; s < 16; s++) {
        w2h[s] = *(const uint2*)(g_B2h + (s * 32 + lane) * 2);
        w2l[s] = *(const uint2*)(g_B2l + (s * 32 + lane) * 2);
    }
    int j = 2 * (lane & 3);
    float b2j0 = b2[j], b2j1 = b2[j + 1];

    unsigned int a_row = (unsigned)(lane & 15);
    unsigned int a_col = (unsigned)((lane >> 4) * 8);

    int n_groups = (n_edges + 15) >> 4;
    for (int grp = blockIdx.x * 8 + warp; grp < n_groups; grp += gridDim.x * 8) {
        long long eBase = (long long)grp * 16;

        // load 16 edges' (r, c): lanes 0-15 hold r, 16-31 hold c
        long long my_e = eBase + (lane & 15);
        if (my_e >= n_edges) my_e = n_edges - 1;
        int rr = (lane < 16) ? ei[my_e] : ei[(long long)n_edges + my_e];
        rr = min(max(rr, 0), n_nodes - 1);

        // gather + h = relu(U' + V), store fp16 rows to warp buffer
#pragma unroll 4
        for (int g = 0; g < 16; g++) {
            int r = __shfl_sync(0xffffffffu, rr, g);
            int c = __shfl_sync(0xffffffffu, rr, 16 + g);
            uint4 u = *(const uint4*)(g_UV + (long long)r * 256 + lane * 4);
            uint4 v = *(const uint4*)(g_UV + (long long)c * 256 + 128 + lane * 4);
            uint4 h;
            h.x = h2_add_relu(u.x, v.x);
            h.y = h2_add_relu(u.y, v.y);
            h.z = h2_add_relu(u.z, v.z);
            h.w = h2_add_relu(u.w, v.w);
            asm volatile("st.shared.v4.b32 [%0], {%1,%2,%3,%4};"
                         :: "r"(hbase + (unsigned)(g * EK_HSTR + lane * 8) * 2),
                            "r"(h.x), "r"(h.y), "r"(h.z), "r"(h.w) : "memory");
        }
        __syncwarp();

        // GEMM2: 16 k-steps, W2 hi + lo
        float cacc[4] = {0.f, 0.f, 0.f, 0.f};
#pragma unroll
        for (int s = 0; s < 16; s++) {
            unsigned int ah[4];
            ldmatrix4(ah, hbase + (a_row * EK_HSTR + s * 16 + a_col) * 2);
            mma_f16(cacc, ah, w2h[s].x, w2h[s].y);
            mma_f16(cacc, ah, w2l[s].x, w2l[s].y);
        }
        __syncwarp();

        // output: lane -> rows (lane>>2), (lane>>2)+8; cols j, j+1
        long long e0 = eBase + (lane >> 2);
        if (e0 < n_edges) {
            float2 o0 = make_float2(cacc[0] + b2j0, cacc[1] + b2j1);
            *(float2*)(out + e0 * ETYPES + j) = o0;
        }
        if (e0 + 8 < n_edges) {
            float2 o1 = make_float2(cacc[2] + b2j0, cacc[3] + b2j1);
            *(float2*)(out + (e0 + 8) * ETYPES + j) = o1;
        }
    }
}

// ---------------- launch ----------------
extern "C" void kernel_launch(void* const* d_in, const int* in_sizes, int n_in,
                              void* d_out, int out_size) {
    const float* z  = (const float*)d_in[0];
    const int*   ei = (const int*)d_in[1];
    const float* Wn = (const float*)d_in[2];
    const float* bn = (const float*)d_in[3];
    const float* W1 = (const float*)d_in[4];
    const float* b1 = (const float*)d_in[5];
    const float* W2 = (const float*)d_in[6];
    const float* b2 = (const float*)d_in[7];

    int n_nodes = in_sizes[0] / LATENT;
    int n_edges = in_sizes[1] / 2;
    float* out = (float*)d_out;

    prep_w1cat<<<32, 256>>>(W1);
    prep_w2<<<2, 256>>>(W2);
    node_kernel<<<(n_nodes + 31) / 32, THREADS>>>(z, Wn, bn, out, n_nodes);

    int mtiles = (n_nodes + 63) / 64;
    cudaFuncSetAttribute(uv_kernel, cudaFuncAttributeMaxDynamicSharedMemorySize, UV_SMEM);
    uv_kernel<<<mtiles * 2, THREADS, UV_SMEM>>>(z, b1, n_nodes);

    cudaFuncSetAttribute(edge_kernel, cudaFuncAttributeMaxDynamicSharedMemorySize, EK_SMEM);
    edge_kernel<<<1250, THREADS, EK_SMEM>>>(ei, b2, out + (size_t)n_nodes * NTYPES,
                                            n_edges, n_nodes);
}

// round 14
// speedup vs baseline: 3.5347x; 1.1328x over previous
#include <cuda_runtime.h>
#include <cuda_fp16.h>
#include <cstdint>

#define LATENT   128
#define HIDDEN   256
#define NTYPES   32
#define ETYPES   8
#define THREADS  256

// ---------- persistent device scratch ----------
__device__ unsigned int g_Bu[16384];
__device__ unsigned int g_Bv[16384];
__device__ unsigned int g_B2h[1024];
__device__ unsigned int g_B2l[1024];
// UV table: per node 512 fp16 (U' cols 0..255 | V cols 256..511), u32 words
__device__ unsigned int g_UV[12812288];

// ---------- helpers ----------
__device__ __forceinline__ unsigned int smem_u32(const void* p) {
    unsigned int a;
    asm("{ .reg .u64 t; cvta.to.shared.u64 t, %1; cvt.u32.u64 %0, t; }" : "=r"(a) : "l"(p));
    return a;
}
__device__ __forceinline__ unsigned int pack_h2(__half a, __half b) {
    __half2 h = __halves2half2(a, b);
    return *reinterpret_cast<unsigned int*>(&h);
}
__device__ __forceinline__ unsigned int pack_f2(float a, float b) {
    return pack_h2(__float2half_rn(a), __float2half_rn(b));
}
__device__ __forceinline__ unsigned int h2_add_relu(unsigned int a, unsigned int b) {
    __half2 s = __hadd2(*reinterpret_cast<__half2*>(&a), *reinterpret_cast<__half2*>(&b));
    __half2 z = __float2half2_rn(0.f);
    s = __hmax2(s, z);
    return *reinterpret_cast<unsigned int*>(&s);
}
__device__ __forceinline__ void mma_f16(float* c, const unsigned int* a,
                                        unsigned int b0, unsigned int b1) {
    asm volatile(
        "mma.sync.aligned.m16n8k16.row.col.f32.f16.f16.f32 "
        "{%0,%1,%2,%3}, {%4,%5,%6,%7}, {%8,%9}, {%0,%1,%2,%3};"
        : "+f"(c[0]), "+f"(c[1]), "+f"(c[2]), "+f"(c[3])
        : "r"(a[0]), "r"(a[1]), "r"(a[2]), "r"(a[3]), "r"(b0), "r"(b1));
}
__device__ __forceinline__ void ldmatrix4(unsigned int* r, unsigned int addr) {
    asm volatile("ldmatrix.sync.aligned.m8n8.x4.shared.b16 {%0,%1,%2,%3}, [%4];"
                 : "=r"(r[0]), "=r"(r[1]), "=r"(r[2]), "=r"(r[3]) : "r"(addr));
}
__device__ __forceinline__ void cp_async16(unsigned int dst, const void* src) {
    asm volatile("cp.async.cg.shared.global [%0], [%1], 16;" :: "r"(dst), "l"(src));
}
__device__ __forceinline__ void cp_commit() {
    asm volatile("cp.async.commit_group;" ::: "memory");
}
__device__ __forceinline__ void cp_wait0() {
    asm volatile("cp.async.wait_group 0;" ::: "memory");
}

// ---------------- prep: pack W1 halves into fragment-ready fp16 ----------------
__global__ void prep_w1cat(const float* __restrict__ W1) {
    int p = blockIdx.x * 256 + threadIdx.x;    // 0..8191: (s<8, T<32, lane<32)
    int l = p & 31;
    int T = (p >> 5) & 31;
    int s = p >> 10;
    int n  = T * 8 + (l >> 2);
    int kb = s * 16 + 2 * (l & 3);
#pragma unroll
    for (int q = 0; q < 2; q++) {
        int k = kb + q * 8;
        g_Bu[p * 2 + q] = pack_f2(W1[k * HIDDEN + n],         W1[(k + 1) * HIDDEN + n]);
        g_Bv[p * 2 + q] = pack_f2(W1[(k + 128) * HIDDEN + n], W1[(k + 129) * HIDDEN + n]);
    }
}

// ---------------- prep: pack W2 into fragment-ready fp16 hi/lo ----------------
__global__ void prep_w2(const float* __restrict__ W2) {
    int p = blockIdx.x * 256 + threadIdx.x;   // 0..511
    if (p >= 512) return;
    int lane = p & 31;
    int g   = lane >> 2;
    int tig = lane & 3;
    int k0  = (p >> 5) * 16 + 2 * tig;
#pragma unroll
    for (int q = 0; q < 2; q++) {
        int k = k0 + q * 8;
        float v0 = W2[k * ETYPES + g];
        float v1 = W2[(k + 1) * ETYPES + g];
        __half h0 = __float2half_rn(v0);
        __half h1 = __float2half_rn(v1);
        g_B2h[p * 2 + q] = pack_h2(h0, h1);
        g_B2l[p * 2 + q] = pack_h2(__float2half_rn(v0 - __half2float(h0)),
                                   __float2half_rn(v1 - __half2float(h1)));
    }
}

// ---------------- node logits ----------------
__global__ void node_kernel(const float* __restrict__ z,
                            const float* __restrict__ Wn,
                            const float* __restrict__ bn,
                            float* __restrict__ out, int n_nodes) {
    __shared__ float ws[LATENT * NTYPES];
    __shared__ float zs[32 * 132];
    __shared__ float bs[NTYPES];
    int tid = threadIdx.x;
    for (int idx = tid; idx < LATENT * NTYPES / 4; idx += THREADS)
        ((float4*)ws)[idx] = ((const float4*)Wn)[idx];
    if (tid < NTYPES) bs[tid] = bn[tid];
    long long nBase = (long long)blockIdx.x * 32;
    for (int idx = tid; idx < 32 * LATENT / 4; idx += THREADS) {
        int n = idx / (LATENT / 4), kk = idx % (LATENT / 4);
        long long gn = nBase + n;
        float4 v = make_float4(0.f, 0.f, 0.f, 0.f);
        if (gn < n_nodes) v = *(const float4*)(z + gn * LATENT + kk * 4);
        *(float4*)(zs + n * 132 + kk * 4) = v;
    }
    __syncthreads();
    int n = tid >> 3, tg = tid & 7;
    float a0 = bs[tg*4+0], a1 = bs[tg*4+1], a2 = bs[tg*4+2], a3 = bs[tg*4+3];
    const float* zr = zs + n * 132;
#pragma unroll 8
    for (int k = 0; k < LATENT; k++) {
        float zv = zr[k];
        float4 w = *(const float4*)(ws + k * NTYPES + tg * 4);
        a0 = fmaf(zv, w.x, a0); a1 = fmaf(zv, w.y, a1);
        a2 = fmaf(zv, w.z, a2); a3 = fmaf(zv, w.w, a3);
    }
    long long gn = nBase + n;
    if (gn < n_nodes)
        *(float4*)(out + gn * NTYPES + tg * 4) = make_float4(a0, a1, a2, a3);
}

// ---------------- uv kernel (unchanged, validated) ----------------
#define UV_ASTR   136
#define UV_SM_B0  (64 * UV_ASTR * 2)          // 17408
#define UV_SMEM   (UV_SM_B0 + 2 * 16384)      // 50176
__global__ void __launch_bounds__(THREADS, 2)
uv_kernel(const float* __restrict__ z,
          const float* __restrict__ b1,
          int n_nodes) {
    extern __shared__ char dsm[];
    __shared__ float b1s[HIDDEN];

    int tid  = threadIdx.x;
    int lane = tid & 31;
    int warp = tid >> 5;
    int mh   = warp >> 2;
    int nq   = warp & 3;
    int p    = blockIdx.x & 1;
    long long nodeBase = (long long)(blockIdx.x >> 1) * 64;

    unsigned int smb = smem_u32(dsm);
    const unsigned int* Bsrc = p ? g_Bv : g_Bu;

    {
        unsigned int dst = smb + UV_SM_B0;
        const uint4* sb = (const uint4*)Bsrc;
#pragma unroll
        for (int u = 0; u < 4; u++)
            cp_async16(dst + (tid + u * THREADS) * 16, sb + tid + u * THREADS);
        cp_commit();
    }

    if (tid < HIDDEN) b1s[tid] = b1[tid];

    {
        int n_l = tid >> 2;
        int q   = tid & 3;
        long long node = nodeBase + n_l;
        if (node >= n_nodes) node = n_nodes - 1;
        const float* src = z + node * LATENT + q * 32;
        unsigned short* A = (unsigned short*)dsm;
        int base = n_l * UV_ASTR + q * 32;
#pragma unroll
        for (int gg = 0; gg < 4; gg++) {
            float4 a = *(const float4*)(src + gg * 8);
            float4 b = *(const float4*)(src + gg * 8 + 4);
            uint4 pk;
            pk.x = pack_f2(a.x, a.y);
            pk.y = pack_f2(a.z, a.w);
            pk.z = pack_f2(b.x, b.y);
            pk.w = pack_f2(b.z, b.w);
            *(uint4*)(A + base + gg * 8) = pk;
        }
    }

    float acc[2][8][4];
#pragma unroll
    for (int i = 0; i < 2; i++)
#pragma unroll
        for (int t = 0; t < 8; t++)
#pragma unroll
            for (int r = 0; r < 4; r++) acc[i][t][r] = 0.f;

    unsigned int a_row = (unsigned)(lane & 15);
    unsigned int a_col = (unsigned)((lane >> 4) * 8);

    for (int c = 0; c < 4; c++) {
        cp_wait0();
        __syncthreads();
        if (c + 1 < 4) {
            unsigned int dst = smb + UV_SM_B0 + ((c + 1) & 1) * 16384;
            const uint4* sb = (const uint4*)(Bsrc + (c + 1) * 4096);
#pragma unroll
            for (int u = 0; u < 4; u++)
                cp_async16(dst + (tid + u * THREADS) * 16, sb + tid + u * THREADS);
            cp_commit();
        }
        unsigned int bbase = smb + UV_SM_B0 + (c & 1) * 16384;
#pragma unroll
        for (int s = 0; s < 2; s++) {
            int k0 = (c * 2 + s) * 16;
            unsigned int bw[8][2];
#pragma unroll
            for (int t = 0; t < 8; t++) {
                int T = nq * 8 + t;
                unsigned int boff = bbase + (((unsigned)(s * 32 + T) * 32 + lane) * 8);
                asm volatile("ld.shared.v2.u32 {%0,%1}, [%2];"
                             : "=r"(bw[t][0]), "=r"(bw[t][1]) : "r"(boff));
            }
#pragma unroll
            for (int i = 0; i < 2; i++) {
                unsigned int ah[4];
                int mrow = (mh * 2 + i) * 16;
                unsigned int off = ((mrow + a_row) * UV_ASTR + k0 + a_col) * 2;
                ldmatrix4(ah, smb + off);
#pragma unroll
                for (int t = 0; t < 8; t++)
                    mma_f16(acc[i][t], ah, bw[t][0], bw[t][1]);
            }
        }
        __syncthreads();
    }

    int g   = lane >> 2;
    int tig = lane & 3;
#pragma unroll
    for (int i = 0; i < 2; i++) {
#pragma unroll
        for (int t = 0; t < 8; t++) {
            int col = nq * 64 + t * 8 + 2 * tig;
            float bb0 = p ? 0.f : b1s[col];
            float bb1 = p ? 0.f : b1s[col + 1];
            long long node0 = nodeBase + (mh * 2 + i) * 16 + g;
            unsigned int h20 = pack_f2(acc[i][t][0] + bb0, acc[i][t][1] + bb1);
            unsigned int h21 = pack_f2(acc[i][t][2] + bb0, acc[i][t][3] + bb1);
            if (node0 < n_nodes)
                g_UV[node0 * 256 + p * 128 + (col >> 1)] = h20;
            if (node0 + 8 < n_nodes)
                g_UV[(node0 + 8) * 256 + p * 128 + (col >> 1)] = h21;
        }
    }
}

// ---------------- edge kernel v3: W2 in smem, 3 CTAs/SM, deep MLP ----------
#define EK_HSTR  264
#define EK_WBUF  (16 * EK_HSTR * 2)           // 8448
#define EK_W2OFF (8 * EK_WBUF)                // 67584
#define EK_SMEM  (EK_W2OFF + 8192)            // 75776
#define EK_GRID  2500
__global__ void __launch_bounds__(THREADS, 3)
edge_kernel(const int* __restrict__ ei,
            const float* __restrict__ b2,
            float* __restrict__ out,
            int n_edges, int n_nodes) {
    extern __shared__ char dsm[];
    int tid  = threadIdx.x;
    int lane = tid & 31;
    int warp = tid >> 5;

    unsigned int smb   = smem_u32(dsm);
    unsigned int hbase = smb + warp * EK_WBUF;
    unsigned int w2b   = smb + EK_W2OFF;

    // stage W2 fragments into smem (hi @0, lo @4096)
    {
        unsigned int* w2s = (unsigned int*)(dsm + EK_W2OFF);
#pragma unroll
        for (int u = 0; u < 4; u++) {
            w2s[tid + u * THREADS]        = g_B2h[tid + u * THREADS];
            w2s[1024 + tid + u * THREADS] = g_B2l[tid + u * THREADS];
        }
    }
    __syncthreads();

    int j = 2 * (lane & 3);
    float b2j0 = b2[j], b2j1 = b2[j + 1];

    unsigned int a_row = (unsigned)(lane & 15);
    unsigned int a_col = (unsigned)((lane >> 4) * 8);

    int n_groups = (n_edges + 15) >> 4;
    int stride = EK_GRID * 8;
    int grp = blockIdx.x * 8 + warp;
    if (grp >= n_groups) return;

    // preload first group's indices
    long long my_e = (long long)grp * 16 + (lane & 15);
    if (my_e >= n_edges) my_e = n_edges - 1;
    int rr = (lane < 16) ? ei[my_e] : ei[(long long)n_edges + my_e];
    rr = min(max(rr, 0), n_nodes - 1);

    for (; grp < n_groups; grp += stride) {
        long long eBase = (long long)grp * 16;

        // gather + h = relu(U' + V): fully unrolled for max MLP
#pragma unroll
        for (int g = 0; g < 16; g++) {
            int r = __shfl_sync(0xffffffffu, rr, g);
            int c = __shfl_sync(0xffffffffu, rr, 16 + g);
            uint4 u = *(const uint4*)(g_UV + (long long)r * 256 + lane * 4);
            uint4 v = *(const uint4*)(g_UV + (long long)c * 256 + 128 + lane * 4);
            uint4 h;
            h.x = h2_add_relu(u.x, v.x);
            h.y = h2_add_relu(u.y, v.y);
            h.z = h2_add_relu(u.z, v.z);
            h.w = h2_add_relu(u.w, v.w);
            asm volatile("st.shared.v4.b32 [%0], {%1,%2,%3,%4};"
                         :: "r"(hbase + (unsigned)(g * EK_HSTR + lane * 8) * 2),
                            "r"(h.x), "r"(h.y), "r"(h.z), "r"(h.w) : "memory");
        }

        // prefetch next group's indices (overlaps with GEMM2)
        int rr_next = rr;
        if (grp + stride < n_groups) {
            long long ne = (long long)(grp + stride) * 16 + (lane & 15);
            if (ne >= n_edges) ne = n_edges - 1;
            rr_next = (lane < 16) ? ei[ne] : ei[(long long)n_edges + ne];
            rr_next = min(max(rr_next, 0), n_nodes - 1);
        }
        __syncwarp();

        // GEMM2: 16 k-steps, W2 hi + lo from smem
        float cacc[4] = {0.f, 0.f, 0.f, 0.f};
#pragma unroll
        for (int s = 0; s < 16; s++) {
            unsigned int ah[4];
            ldmatrix4(ah, hbase + (a_row * EK_HSTR + s * 16 + a_col) * 2);
            unsigned int bh0, bh1, bl0, bl1;
            unsigned int woff = w2b + ((unsigned)(s * 32 + lane)) * 8;
            asm volatile("ld.shared.v2.u32 {%0,%1}, [%2];" : "=r"(bh0), "=r"(bh1) : "r"(woff));
            asm volatile("ld.shared.v2.u32 {%0,%1}, [%2];" : "=r"(bl0), "=r"(bl1) : "r"(woff + 4096));
            mma_f16(cacc, ah, bh0, bh1);
            mma_f16(cacc, ah, bl0, bl1);
        }
        __syncwarp();

        long long e0 = eBase + (lane >> 2);
        if (e0 < n_edges) {
            float2 o0 = make_float2(cacc[0] + b2j0, cacc[1] + b2j1);
            *(float2*)(out + e0 * ETYPES + j) = o0;
        }
        if (e0 + 8 < n_edges) {
            float2 o1 = make_float2(cacc[2] + b2j0, cacc[3] + b2j1);
            *(float2*)(out + (e0 + 8) * ETYPES + j) = o1;
        }
        rr = rr_next;
    }
}

// ---------------- launch ----------------
extern "C" void kernel_launch(void* const* d_in, const int* in_sizes, int n_in,
                              void* d_out, int out_size) {
    const float* z  = (const float*)d_in[0];
    const int*   ei = (const int*)d_in[1];
    const float* Wn = (const float*)d_in[2];
    const float* bn = (const float*)d_in[3];
    const float* W1 = (const float*)d_in[4];
    const float* b1 = (const float*)d_in[5];
    const float* W2 = (const float*)d_in[6];
    const float* b2 = (const float*)d_in[7];

    int n_nodes = in_sizes[0] / LATENT;
    int n_edges = in_sizes[1] / 2;
    float* out = (float*)d_out;

    prep_w1cat<<<32, 256>>>(W1);
    prep_w2<<<2, 256>>>(W2);
    node_kernel<<<(n_nodes + 31) / 32, THREADS>>>(z, Wn, bn, out, n_nodes);

    int mtiles = (n_nodes + 63) / 64;
    cudaFuncSetAttribute(uv_kernel, cudaFuncAttributeMaxDynamicSharedMemorySize, UV_SMEM);
    uv_kernel<<<mtiles * 2, THREADS, UV_SMEM>>>(z, b1, n_nodes);

    cudaFuncSetAttribute(edge_kernel, cudaFuncAttributeMaxDynamicSharedMemorySize, EK_SMEM);
    edge_kernel<<<EK_GRID, THREADS, EK_SMEM>>>(ei, b2, out + (size_t)n_nodes * NTYPES,
                                               n_edges, n_nodes);
}

// round 15
// speedup vs baseline: 3.6710x; 1.0386x over previous
#include <cuda_runtime.h>
#include <cuda_fp16.h>
#include <cstdint>

#define LATENT   128
#define HIDDEN   256
#define NTYPES   32
#define ETYPES   8
#define THREADS  256

// ---------- persistent device scratch ----------
// W1 fragment packs, T-pair v4 layout: word idx = ((s*16 + T/2)*32 + lane)*4 + (T&1)*2 + q
__device__ unsigned int g_Bu[16384];
__device__ unsigned int g_Bv[16384];
// W2 fragments interleaved hi/lo: word idx = (kstep*32 + lane)*4 + {h0,h1,l0,l1}
__device__ unsigned int g_B2[2048];
// UV table: per node 512 fp16 (U' cols 0..255 | V cols 256..511), u32 words
__device__ unsigned int g_UV[12812288];

// ---------- helpers ----------
__device__ __forceinline__ unsigned int smem_u32(const void* p) {
    unsigned int a;
    asm("{ .reg .u64 t; cvta.to.shared.u64 t, %1; cvt.u32.u64 %0, t; }" : "=r"(a) : "l"(p));
    return a;
}
__device__ __forceinline__ unsigned int pack_h2(__half a, __half b) {
    __half2 h = __halves2half2(a, b);
    return *reinterpret_cast<unsigned int*>(&h);
}
__device__ __forceinline__ unsigned int pack_f2(float a, float b) {
    return pack_h2(__float2half_rn(a), __float2half_rn(b));
}
__device__ __forceinline__ unsigned int h2_add_relu(unsigned int a, unsigned int b) {
    __half2 s = __hadd2(*reinterpret_cast<__half2*>(&a), *reinterpret_cast<__half2*>(&b));
    __half2 z = __float2half2_rn(0.f);
    s = __hmax2(s, z);
    return *reinterpret_cast<unsigned int*>(&s);
}
__device__ __forceinline__ void mma_f16(float* c, const unsigned int* a,
                                        unsigned int b0, unsigned int b1) {
    asm volatile(
        "mma.sync.aligned.m16n8k16.row.col.f32.f16.f16.f32 "
        "{%0,%1,%2,%3}, {%4,%5,%6,%7}, {%8,%9}, {%0,%1,%2,%3};"
        : "+f"(c[0]), "+f"(c[1]), "+f"(c[2]), "+f"(c[3])
        : "r"(a[0]), "r"(a[1]), "r"(a[2]), "r"(a[3]), "r"(b0), "r"(b1));
}
__device__ __forceinline__ void ldmatrix4(unsigned int* r, unsigned int addr) {
    asm volatile("ldmatrix.sync.aligned.m8n8.x4.shared.b16 {%0,%1,%2,%3}, [%4];"
                 : "=r"(r[0]), "=r"(r[1]), "=r"(r[2]), "=r"(r[3]) : "r"(addr));
}
__device__ __forceinline__ void cp_async16(unsigned int dst, const void* src) {
    asm volatile("cp.async.cg.shared.global [%0], [%1], 16;" :: "r"(dst), "l"(src));
}
__device__ __forceinline__ void cp_commit() {
    asm volatile("cp.async.commit_group;" ::: "memory");
}
__device__ __forceinline__ void cp_wait0() {
    asm volatile("cp.async.wait_group 0;" ::: "memory");
}

// ---------------- prep: W1 (T-pair v4) + W2 (interleaved hi/lo), one launch ----
__global__ void prep_all(const float* __restrict__ W1, const float* __restrict__ W2) {
    int b = blockIdx.x;
    int tid = threadIdx.x;
    if (b < 32) {
        int p = b * 256 + tid;                 // (s<8, T<32, l<32)
        int l = p & 31;
        int T = (p >> 5) & 31;
        int s = p >> 10;
        int n  = T * 8 + (l >> 2);
        int kb = s * 16 + 2 * (l & 3);
        int dst = (((s * 16 + (T >> 1)) * 32 + l) << 2) + ((T & 1) * 2);
#pragma unroll
        for (int q = 0; q < 2; q++) {
            int k = kb + q * 8;
            g_Bu[dst + q] = pack_f2(W1[k * HIDDEN + n],         W1[(k + 1) * HIDDEN + n]);
            g_Bv[dst + q] = pack_f2(W1[(k + 128) * HIDDEN + n], W1[(k + 129) * HIDDEN + n]);
        }
    } else {
        int p = (b - 32) * 256 + tid;          // 0..511 (kstep<16, lane<32)
        if (p >= 512) return;
        int lane = p & 31;
        int g   = lane >> 2;
        int tig = lane & 3;
        int k0  = (p >> 5) * 16 + 2 * tig;
#pragma unroll
        for (int q = 0; q < 2; q++) {
            int k = k0 + q * 8;
            float v0 = W2[k * ETYPES + g];
            float v1 = W2[(k + 1) * ETYPES + g];
            __half h0 = __float2half_rn(v0);
            __half h1 = __float2half_rn(v1);
            g_B2[p * 4 + q]     = pack_h2(h0, h1);
            g_B2[p * 4 + 2 + q] = pack_h2(__float2half_rn(v0 - __half2float(h0)),
                                          __float2half_rn(v1 - __half2float(h1)));
        }
    }
}

// ---------------- node logits ----------------
__global__ void node_kernel(const float* __restrict__ z,
                            const float* __restrict__ Wn,
                            const float* __restrict__ bn,
                            float* __restrict__ out, int n_nodes) {
    __shared__ float ws[LATENT * NTYPES];
    __shared__ float zs[32 * 132];
    __shared__ float bs[NTYPES];
    int tid = threadIdx.x;
    for (int idx = tid; idx < LATENT * NTYPES / 4; idx += THREADS)
        ((float4*)ws)[idx] = ((const float4*)Wn)[idx];
    if (tid < NTYPES) bs[tid] = bn[tid];
    long long nBase = (long long)blockIdx.x * 32;
    for (int idx = tid; idx < 32 * LATENT / 4; idx += THREADS) {
        int n = idx / (LATENT / 4), kk = idx % (LATENT / 4);
        long long gn = nBase + n;
        float4 v = make_float4(0.f, 0.f, 0.f, 0.f);
        if (gn < n_nodes) v = *(const float4*)(z + gn * LATENT + kk * 4);
        *(float4*)(zs + n * 132 + kk * 4) = v;
    }
    __syncthreads();
    int n = tid >> 3, tg = tid & 7;
    float a0 = bs[tg*4+0], a1 = bs[tg*4+1], a2 = bs[tg*4+2], a3 = bs[tg*4+3];
    const float* zr = zs + n * 132;
#pragma unroll 8
    for (int k = 0; k < LATENT; k++) {
        float zv = zr[k];
        float4 w = *(const float4*)(ws + k * NTYPES + tg * 4);
        a0 = fmaf(zv, w.x, a0); a1 = fmaf(zv, w.y, a1);
        a2 = fmaf(zv, w.z, a2); a3 = fmaf(zv, w.w, a3);
    }
    long long gn = nBase + n;
    if (gn < n_nodes)
        *(float4*)(out + gn * NTYPES + tg * 4) = make_float4(a0, a1, a2, a3);
}

// ---------------- uv kernel: single-shot B, one sync, v4 B-frag loads ----------
#define UV_ASTR   136
#define UV_SM_B0  (64 * UV_ASTR * 2)          // 17408
#define UV_SMEM   (UV_SM_B0 + 65536)          // 82944
__global__ void __launch_bounds__(THREADS, 2)
uv_kernel(const float* __restrict__ z,
          const float* __restrict__ b1,
          int n_nodes) {
    extern __shared__ char dsm[];
    __shared__ float b1s[HIDDEN];

    int tid  = threadIdx.x;
    int lane = tid & 31;
    int warp = tid >> 5;
    int mh   = warp >> 2;
    int nq   = warp & 3;
    int p    = blockIdx.x & 1;
    long long nodeBase = (long long)(blockIdx.x >> 1) * 64;

    unsigned int smb = smem_u32(dsm);
    const unsigned int* Bsrc = p ? g_Bv : g_Bu;

    // stage ALL of B (64 KB) via cp.async, overlapped with A staging below
    {
        unsigned int dst = smb + UV_SM_B0;
        const uint4* sb = (const uint4*)Bsrc;
#pragma unroll
        for (int u = 0; u < 16; u++)
            cp_async16(dst + (tid + u * THREADS) * 16, sb + tid + u * THREADS);
        cp_commit();
    }

    if (tid < HIDDEN) b1s[tid] = b1[tid];

    // stage A: 64 nodes x 128 k fp16
    {
        int n_l = tid >> 2;
        int q   = tid & 3;
        long long node = nodeBase + n_l;
        if (node >= n_nodes) node = n_nodes - 1;
        const float* src = z + node * LATENT + q * 32;
        unsigned short* A = (unsigned short*)dsm;
        int base = n_l * UV_ASTR + q * 32;
#pragma unroll
        for (int gg = 0; gg < 4; gg++) {
            float4 a = *(const float4*)(src + gg * 8);
            float4 b = *(const float4*)(src + gg * 8 + 4);
            uint4 pk;
            pk.x = pack_f2(a.x, a.y);
            pk.y = pack_f2(a.z, a.w);
            pk.z = pack_f2(b.x, b.y);
            pk.w = pack_f2(b.z, b.w);
            *(uint4*)(A + base + gg * 8) = pk;
        }
    }

    float acc[2][8][4];
#pragma unroll
    for (int i = 0; i < 2; i++)
#pragma unroll
        for (int t = 0; t < 8; t++)
#pragma unroll
            for (int r = 0; r < 4; r++) acc[i][t][r] = 0.f;

    unsigned int a_row = (unsigned)(lane & 15);
    unsigned int a_col = (unsigned)((lane >> 4) * 8);
    unsigned int bbase = smb + UV_SM_B0;

    cp_wait0();
    __syncthreads();

#pragma unroll
    for (int s = 0; s < 8; s++) {
        int k0 = s * 16;
        // 4 x ld.v4: each holds fragments for a T-pair
        unsigned int bw[8][2];
#pragma unroll
        for (int tt = 0; tt < 4; tt++) {
            unsigned int boff = bbase + (((unsigned)(s * 16 + nq * 4 + tt) * 32 + lane) << 4);
            uint4 v;
            asm volatile("ld.shared.v4.u32 {%0,%1,%2,%3}, [%4];"
                         : "=r"(v.x), "=r"(v.y), "=r"(v.z), "=r"(v.w) : "r"(boff));
            bw[2 * tt][0]     = v.x; bw[2 * tt][1]     = v.y;
            bw[2 * tt + 1][0] = v.z; bw[2 * tt + 1][1] = v.w;
        }
#pragma unroll
        for (int i = 0; i < 2; i++) {
            unsigned int ah[4];
            int mrow = (mh * 2 + i) * 16;
            unsigned int off = ((mrow + a_row) * UV_ASTR + k0 + a_col) * 2;
            ldmatrix4(ah, smb + off);
#pragma unroll
            for (int t = 0; t < 8; t++)
                mma_f16(acc[i][t], ah, bw[t][0], bw[t][1]);
        }
    }

    // epilogue: (+b1 for U-half), cvt fp16, store to g_UV
    int g   = lane >> 2;
    int tig = lane & 3;
#pragma unroll
    for (int i = 0; i < 2; i++) {
#pragma unroll
        for (int t = 0; t < 8; t++) {
            int col = nq * 64 + t * 8 + 2 * tig;
            float bb0 = p ? 0.f : b1s[col];
            float bb1 = p ? 0.f : b1s[col + 1];
            long long node0 = nodeBase + (mh * 2 + i) * 16 + g;
            unsigned int h20 = pack_f2(acc[i][t][0] + bb0, acc[i][t][1] + bb1);
            unsigned int h21 = pack_f2(acc[i][t][2] + bb0, acc[i][t][3] + bb1);
            if (node0 < n_nodes)
                g_UV[node0 * 256 + p * 128 + (col >> 1)] = h20;
            if (node0 + 8 < n_nodes)
                g_UV[(node0 + 8) * 256 + p * 128 + (col >> 1)] = h21;
        }
    }
}

// ---------------- edge kernel: W2 v4 in smem, 3 CTAs/SM, deep MLP ----------
#define EK_HSTR  264
#define EK_WBUF  (16 * EK_HSTR * 2)           // 8448
#define EK_W2OFF (8 * EK_WBUF)                // 67584
#define EK_SMEM  (EK_W2OFF + 8192)            // 75776
#define EK_GRID  2500
__global__ void __launch_bounds__(THREADS, 3)
edge_kernel(const int* __restrict__ ei,
            const float* __restrict__ b2,
            float* __restrict__ out,
            int n_edges, int n_nodes) {
    extern __shared__ char dsm[];
    int tid  = threadIdx.x;
    int lane = tid & 31;
    int warp = tid >> 5;

    unsigned int smb   = smem_u32(dsm);
    unsigned int hbase = smb + warp * EK_WBUF;
    unsigned int w2b   = smb + EK_W2OFF;

    // stage W2 fragments (interleaved hi/lo) into smem: 2048 words
    {
        unsigned int* w2s = (unsigned int*)(dsm + EK_W2OFF);
#pragma unroll
        for (int u = 0; u < 8; u++)
            w2s[tid + u * THREADS] = g_B2[tid + u * THREADS];
    }
    __syncthreads();

    int j = 2 * (lane & 3);
    float b2j0 = b2[j], b2j1 = b2[j + 1];

    unsigned int a_row = (unsigned)(lane & 15);
    unsigned int a_col = (unsigned)((lane >> 4) * 8);

    int n_groups = (n_edges + 15) >> 4;
    int stride = EK_GRID * 8;
    int grp = blockIdx.x * 8 + warp;
    if (grp >= n_groups) return;

    // preload first group's indices
    long long my_e = (long long)grp * 16 + (lane & 15);
    if (my_e >= n_edges) my_e = n_edges - 1;
    int rr = (lane < 16) ? ei[my_e] : ei[(long long)n_edges + my_e];
    rr = min(max(rr, 0), n_nodes - 1);

    for (; grp < n_groups; grp += stride) {
        long long eBase = (long long)grp * 16;

        // gather + h = relu(U' + V): fully unrolled for max MLP
#pragma unroll
        for (int g = 0; g < 16; g++) {
            int r = __shfl_sync(0xffffffffu, rr, g);
            int c = __shfl_sync(0xffffffffu, rr, 16 + g);
            uint4 u = *(const uint4*)(g_UV + (long long)r * 256 + lane * 4);
            uint4 v = *(const uint4*)(g_UV + (long long)c * 256 + 128 + lane * 4);
            uint4 h;
            h.x = h2_add_relu(u.x, v.x);
            h.y = h2_add_relu(u.y, v.y);
            h.z = h2_add_relu(u.z, v.z);
            h.w = h2_add_relu(u.w, v.w);
            asm volatile("st.shared.v4.b32 [%0], {%1,%2,%3,%4};"
                         :: "r"(hbase + (unsigned)(g * EK_HSTR + lane * 8) * 2),
                            "r"(h.x), "r"(h.y), "r"(h.z), "r"(h.w) : "memory");
        }

        // prefetch next group's indices (overlaps with GEMM2)
        int rr_next = rr;
        if (grp + stride < n_groups) {
            long long ne = (long long)(grp + stride) * 16 + (lane & 15);
            if (ne >= n_edges) ne = n_edges - 1;
            rr_next = (lane < 16) ? ei[ne] : ei[(long long)n_edges + ne];
            rr_next = min(max(rr_next, 0), n_nodes - 1);
        }
        __syncwarp();

        // GEMM2: 16 k-steps, one v4 W2 load per step (hi+lo)
        float cacc[4] = {0.f, 0.f, 0.f, 0.f};
#pragma unroll
        for (int s = 0; s < 16; s++) {
            unsigned int ah[4];
            ldmatrix4(ah, hbase + (a_row * EK_HSTR + s * 16 + a_col) * 2);
            uint4 w;
            unsigned int woff = w2b + ((unsigned)(s * 32 + lane) << 4);
            asm volatile("ld.shared.v4.u32 {%0,%1,%2,%3}, [%4];"
                         : "=r"(w.x), "=r"(w.y), "=r"(w.z), "=r"(w.w) : "r"(woff));
            mma_f16(cacc, ah, w.x, w.y);
            mma_f16(cacc, ah, w.z, w.w);
        }
        __syncwarp();

        long long e0 = eBase + (lane >> 2);
        if (e0 < n_edges) {
            float2 o0 = make_float2(cacc[0] + b2j0, cacc[1] + b2j1);
            *(float2*)(out + e0 * ETYPES + j) = o0;
        }
        if (e0 + 8 < n_edges) {
            float2 o1 = make_float2(cacc[2] + b2j0, cacc[3] + b2j1);
            *(float2*)(out + (e0 + 8) * ETYPES + j) = o1;
        }
        rr = rr_next;
    }
}

// ---------------- launch ----------------
extern "C" void kernel_launch(void* const* d_in, const int* in_sizes, int n_in,
                              void* d_out, int out_size) {
    const float* z  = (const float*)d_in[0];
    const int*   ei = (const int*)d_in[1];
    const float* Wn = (const float*)d_in[2];
    const float* bn = (const float*)d_in[3];
    const float* W1 = (const float*)d_in[4];
    const float* b1 = (const float*)d_in[5];
    const float* W2 = (const float*)d_in[6];
    const float* b2 = (const float*)d_in[7];

    int n_nodes = in_sizes[0] / LATENT;
    int n_edges = in_sizes[1] / 2;
    float* out = (float*)d_out;

    prep_all<<<34, 256>>>(W1, W2);
    node_kernel<<<(n_nodes + 31) / 32, THREADS>>>(z, Wn, bn, out, n_nodes);

    int mtiles = (n_nodes + 63) / 64;
    cudaFuncSetAttribute(uv_kernel, cudaFuncAttributeMaxDynamicSharedMemorySize, UV_SMEM);
    uv_kernel<<<mtiles * 2, THREADS, UV_SMEM>>>(z, b1, n_nodes);

    cudaFuncSetAttribute(edge_kernel, cudaFuncAttributeMaxDynamicSharedMemorySize, EK_SMEM);
    edge_kernel<<<EK_GRID, THREADS, EK_SMEM>>>(ei, b2, out + (size_t)n_nodes * NTYPES,
                                               n_edges, n_nodes);
}

// round 16
// speedup vs baseline: 3.8369x; 1.0452x over previous
#include <cuda_runtime.h>
#include <cuda_fp16.h>
#include <cstdint>

#define LATENT   128
#define HIDDEN   256
#define NTYPES   32
#define ETYPES   8
#define THREADS  256

// ---------- persistent device scratch ----------
// W1 fragment packs, T-pair v4 layout: word idx = ((s*16 + T/2)*32 + lane)*4 + (T&1)*2 + q
__device__ unsigned int g_Bu[16384];
__device__ unsigned int g_Bv[16384];
// W2 fragments (hi only): word idx = (kstep*32 + lane)*2 + q
__device__ unsigned int g_B2[1024];
// UV table: per node 512 fp16 (U' cols 0..255 | V cols 256..511), u32 words
__device__ unsigned int g_UV[12812288];

// ---------- helpers ----------
__device__ __forceinline__ unsigned int smem_u32(const void* p) {
    unsigned int a;
    asm("{ .reg .u64 t; cvta.to.shared.u64 t, %1; cvt.u32.u64 %0, t; }" : "=r"(a) : "l"(p));
    return a;
}
__device__ __forceinline__ unsigned int pack_h2(__half a, __half b) {
    __half2 h = __halves2half2(a, b);
    return *reinterpret_cast<unsigned int*>(&h);
}
__device__ __forceinline__ unsigned int pack_f2(float a, float b) {
    return pack_h2(__float2half_rn(a), __float2half_rn(b));
}
__device__ __forceinline__ unsigned int h2_add_relu(unsigned int a, unsigned int b) {
    __half2 s = __hadd2(*reinterpret_cast<__half2*>(&a), *reinterpret_cast<__half2*>(&b));
    __half2 z = __float2half2_rn(0.f);
    s = __hmax2(s, z);
    return *reinterpret_cast<unsigned int*>(&s);
}
__device__ __forceinline__ void mma_f16(float* c, const unsigned int* a,
                                        unsigned int b0, unsigned int b1) {
    asm volatile(
        "mma.sync.aligned.m16n8k16.row.col.f32.f16.f16.f32 "
        "{%0,%1,%2,%3}, {%4,%5,%6,%7}, {%8,%9}, {%0,%1,%2,%3};"
        : "+f"(c[0]), "+f"(c[1]), "+f"(c[2]), "+f"(c[3])
        : "r"(a[0]), "r"(a[1]), "r"(a[2]), "r"(a[3]), "r"(b0), "r"(b1));
}
__device__ __forceinline__ void ldmatrix4(unsigned int* r, unsigned int addr) {
    asm volatile("ldmatrix.sync.aligned.m8n8.x4.shared.b16 {%0,%1,%2,%3}, [%4];"
                 : "=r"(r[0]), "=r"(r[1]), "=r"(r[2]), "=r"(r[3]) : "r"(addr));
}
__device__ __forceinline__ void cp_async16(unsigned int dst, const void* src) {
    asm volatile("cp.async.cg.shared.global [%0], [%1], 16;" :: "r"(dst), "l"(src));
}
__device__ __forceinline__ void cp_commit() {
    asm volatile("cp.async.commit_group;" ::: "memory");
}
__device__ __forceinline__ void cp_wait0() {
    asm volatile("cp.async.wait_group 0;" ::: "memory");
}

// ---------------- prep: W1 (T-pair v4) + W2 (hi only), one launch ----------
__global__ void prep_all(const float* __restrict__ W1, const float* __restrict__ W2) {
    int b = blockIdx.x;
    int tid = threadIdx.x;
    if (b < 32) {
        int p = b * 256 + tid;                 // (s<8, T<32, l<32)
        int l = p & 31;
        int T = (p >> 5) & 31;
        int s = p >> 10;
        int n  = T * 8 + (l >> 2);
        int kb = s * 16 + 2 * (l & 3);
        int dst = (((s * 16 + (T >> 1)) * 32 + l) << 2) + ((T & 1) * 2);
#pragma unroll
        for (int q = 0; q < 2; q++) {
            int k = kb + q * 8;
            g_Bu[dst + q] = pack_f2(W1[k * HIDDEN + n],         W1[(k + 1) * HIDDEN + n]);
            g_Bv[dst + q] = pack_f2(W1[(k + 128) * HIDDEN + n], W1[(k + 129) * HIDDEN + n]);
        }
    } else {
        int p = (b - 32) * 256 + tid;          // 0..511 (kstep<16, lane<32)
        if (p >= 512) return;
        int lane = p & 31;
        int g   = lane >> 2;
        int tig = lane & 3;
        int k0  = (p >> 5) * 16 + 2 * tig;
#pragma unroll
        for (int q = 0; q < 2; q++) {
            int k = k0 + q * 8;
            g_B2[p * 2 + q] = pack_f2(W2[k * ETYPES + g], W2[(k + 1) * ETYPES + g]);
        }
    }
}

// ---------------- fused uv + node kernel ----------------
// blocks [0, n_uv): UV precompute (p = blk&1: 0 U-half +b1, 1 V-half)
// blocks [n_uv, n_uv + n_node_tiles): node logits (32 nodes per block)
#define UV_ASTR   136
#define UV_SM_B0  (64 * UV_ASTR * 2)          // 17408
#define UV_SMEM   (UV_SM_B0 + 65536)          // 82944
__global__ void __launch_bounds__(THREADS, 2)
uv_node_kernel(const float* __restrict__ z,
               const float* __restrict__ b1,
               const float* __restrict__ Wn,
               const float* __restrict__ bn,
               float* __restrict__ node_out,
               int n_nodes, int n_uv) {
    extern __shared__ char dsm[];
    __shared__ float b1s[HIDDEN];

    int tid  = threadIdx.x;
    int lane = tid & 31;
    int warp = tid >> 5;

    if ((int)blockIdx.x >= n_uv) {
        // ---------------- node-logits branch (smem overlays dynamic region) ----
        float* ws = (float*)dsm;               // 4096 floats
        float* zs = ws + LATENT * NTYPES;      // 32*132
        float* bs = zs + 32 * 132;             // 32
        int nb = blockIdx.x - n_uv;

        for (int idx = tid; idx < LATENT * NTYPES / 4; idx += THREADS)
            ((float4*)ws)[idx] = ((const float4*)Wn)[idx];
        if (tid < NTYPES) bs[tid] = bn[tid];
        long long nBase = (long long)nb * 32;
        for (int idx = tid; idx < 32 * LATENT / 4; idx += THREADS) {
            int n = idx / (LATENT / 4), kk = idx % (LATENT / 4);
            long long gn = nBase + n;
            float4 v = make_float4(0.f, 0.f, 0.f, 0.f);
            if (gn < n_nodes) v = *(const float4*)(z + gn * LATENT + kk * 4);
            *(float4*)(zs + n * 132 + kk * 4) = v;
        }
        __syncthreads();
        int n = tid >> 3, tg = tid & 7;
        float a0 = bs[tg*4+0], a1 = bs[tg*4+1], a2 = bs[tg*4+2], a3 = bs[tg*4+3];
        const float* zr = zs + n * 132;
#pragma unroll 8
        for (int k = 0; k < LATENT; k++) {
            float zv = zr[k];
            float4 w = *(const float4*)(ws + k * NTYPES + tg * 4);
            a0 = fmaf(zv, w.x, a0); a1 = fmaf(zv, w.y, a1);
            a2 = fmaf(zv, w.z, a2); a3 = fmaf(zv, w.w, a3);
        }
        long long gn = nBase + n;
        if (gn < n_nodes)
            *(float4*)(node_out + gn * NTYPES + tg * 4) = make_float4(a0, a1, a2, a3);
        return;
    }

    // ---------------- UV branch ----------------
    int mh   = warp >> 2;
    int nq   = warp & 3;
    int p    = blockIdx.x & 1;
    long long nodeBase = (long long)(blockIdx.x >> 1) * 64;

    unsigned int smb = smem_u32(dsm);
    const unsigned int* Bsrc = p ? g_Bv : g_Bu;

    // stage ALL of B (64 KB) via cp.async, overlapped with A staging below
    {
        unsigned int dst = smb + UV_SM_B0;
        const uint4* sb = (const uint4*)Bsrc;
#pragma unroll
        for (int u = 0; u < 16; u++)
            cp_async16(dst + (tid + u * THREADS) * 16, sb + tid + u * THREADS);
        cp_commit();
    }

    if (tid < HIDDEN) b1s[tid] = b1[tid];

    // stage A: 64 nodes x 128 k fp16
    {
        int n_l = tid >> 2;
        int q   = tid & 3;
        long long node = nodeBase + n_l;
        if (node >= n_nodes) node = n_nodes - 1;
        const float* src = z + node * LATENT + q * 32;
        unsigned short* A = (unsigned short*)dsm;
        int base = n_l * UV_ASTR + q * 32;
#pragma unroll
        for (int gg = 0; gg < 4; gg++) {
            float4 a = *(const float4*)(src + gg * 8);
            float4 b = *(const float4*)(src + gg * 8 + 4);
            uint4 pk;
            pk.x = pack_f2(a.x, a.y);
            pk.y = pack_f2(a.z, a.w);
            pk.z = pack_f2(b.x, b.y);
            pk.w = pack_f2(b.z, b.w);
            *(uint4*)(A + base + gg * 8) = pk;
        }
    }

    float acc[2][8][4];
#pragma unroll
    for (int i = 0; i < 2; i++)
#pragma unroll
        for (int t = 0; t < 8; t++)
#pragma unroll
            for (int r = 0; r < 4; r++) acc[i][t][r] = 0.f;

    unsigned int a_row = (unsigned)(lane & 15);
    unsigned int a_col = (unsigned)((lane >> 4) * 8);
    unsigned int bbase = smb + UV_SM_B0;

    cp_wait0();
    __syncthreads();

#pragma unroll
    for (int s = 0; s < 8; s++) {
        int k0 = s * 16;
        unsigned int bw[8][2];
#pragma unroll
        for (int tt = 0; tt < 4; tt++) {
            unsigned int boff = bbase + (((unsigned)(s * 16 + nq * 4 + tt) * 32 + lane) << 4);
            uint4 v;
            asm volatile("ld.shared.v4.u32 {%0,%1,%2,%3}, [%4];"
                         : "=r"(v.x), "=r"(v.y), "=r"(v.z), "=r"(v.w) : "r"(boff));
            bw[2 * tt][0]     = v.x; bw[2 * tt][1]     = v.y;
            bw[2 * tt + 1][0] = v.z; bw[2 * tt + 1][1] = v.w;
        }
#pragma unroll
        for (int i = 0; i < 2; i++) {
            unsigned int ah[4];
            int mrow = (mh * 2 + i) * 16;
            unsigned int off = ((mrow + a_row) * UV_ASTR + k0 + a_col) * 2;
            ldmatrix4(ah, smb + off);
#pragma unroll
            for (int t = 0; t < 8; t++)
                mma_f16(acc[i][t], ah, bw[t][0], bw[t][1]);
        }
    }

    // epilogue: (+b1 for U-half), cvt fp16, store to g_UV
    int g   = lane >> 2;
    int tig = lane & 3;
#pragma unroll
    for (int i = 0; i < 2; i++) {
#pragma unroll
        for (int t = 0; t < 8; t++) {
            int col = nq * 64 + t * 8 + 2 * tig;
            float bb0 = p ? 0.f : b1s[col];
            float bb1 = p ? 0.f : b1s[col + 1];
            long long node0 = nodeBase + (mh * 2 + i) * 16 + g;
            unsigned int h20 = pack_f2(acc[i][t][0] + bb0, acc[i][t][1] + bb1);
            unsigned int h21 = pack_f2(acc[i][t][2] + bb0, acc[i][t][3] + bb1);
            if (node0 < n_nodes)
                g_UV[node0 * 256 + p * 128 + (col >> 1)] = h20;
            if (node0 + 8 < n_nodes)
                g_UV[(node0 + 8) * 256 + p * 128 + (col >> 1)] = h21;
        }
    }
}

// ---------------- edge kernel: W2 hi-only in smem, 3 CTAs/SM ----------
#define EK_HSTR  264
#define EK_WBUF  (16 * EK_HSTR * 2)           // 8448
#define EK_W2OFF (8 * EK_WBUF)                // 67584
#define EK_SMEM  (EK_W2OFF + 4096)            // 71680
#define EK_GRID  2500
__global__ void __launch_bounds__(THREADS, 3)
edge_kernel(const int* __restrict__ ei,
            const float* __restrict__ b2,
            float* __restrict__ out,
            int n_edges, int n_nodes) {
    extern __shared__ char dsm[];
    int tid  = threadIdx.x;
    int lane = tid & 31;
    int warp = tid >> 5;

    unsigned int smb   = smem_u32(dsm);
    unsigned int hbase = smb + warp * EK_WBUF;
    unsigned int w2b   = smb + EK_W2OFF;

    // stage W2 fragments (hi) into smem: 1024 words
    {
        unsigned int* w2s = (unsigned int*)(dsm + EK_W2OFF);
#pragma unroll
        for (int u = 0; u < 4; u++)
            w2s[tid + u * THREADS] = g_B2[tid + u * THREADS];
    }
    __syncthreads();

    int j = 2 * (lane & 3);
    float b2j0 = b2[j], b2j1 = b2[j + 1];

    unsigned int a_row = (unsigned)(lane & 15);
    unsigned int a_col = (unsigned)((lane >> 4) * 8);

    int n_groups = (n_edges + 15) >> 4;
    int stride = EK_GRID * 8;
    int grp = blockIdx.x * 8 + warp;
    if (grp >= n_groups) return;

    // preload first group's indices
    long long my_e = (long long)grp * 16 + (lane & 15);
    if (my_e >= n_edges) my_e = n_edges - 1;
    int rr = (lane < 16) ? ei[my_e] : ei[(long long)n_edges + my_e];
    rr = min(max(rr, 0), n_nodes - 1);

    for (; grp < n_groups; grp += stride) {
        long long eBase = (long long)grp * 16;

        // gather + h = relu(U' + V)
#pragma unroll
        for (int g = 0; g < 16; g++) {
            int r = __shfl_sync(0xffffffffu, rr, g);
            int c = __shfl_sync(0xffffffffu, rr, 16 + g);
            uint4 u = *(const uint4*)(g_UV + (long long)r * 256 + lane * 4);
            uint4 v = *(const uint4*)(g_UV + (long long)c * 256 + 128 + lane * 4);
            uint4 h;
            h.x = h2_add_relu(u.x, v.x);
            h.y = h2_add_relu(u.y, v.y);
            h.z = h2_add_relu(u.z, v.z);
            h.w = h2_add_relu(u.w, v.w);
            asm volatile("st.shared.v4.b32 [%0], {%1,%2,%3,%4};"
                         :: "r"(hbase + (unsigned)(g * EK_HSTR + lane * 8) * 2),
                            "r"(h.x), "r"(h.y), "r"(h.z), "r"(h.w) : "memory");
        }

        // prefetch next group's indices (overlaps with GEMM2)
        int rr_next = rr;
        if (grp + stride < n_groups) {
            long long ne = (long long)(grp + stride) * 16 + (lane & 15);
            if (ne >= n_edges) ne = n_edges - 1;
            rr_next = (lane < 16) ? ei[ne] : ei[(long long)n_edges + ne];
            rr_next = min(max(rr_next, 0), n_nodes - 1);
        }
        __syncwarp();

        // GEMM2: 16 k-steps, one v2 W2 load + one MMA per step
        float cacc[4] = {0.f, 0.f, 0.f, 0.f};
#pragma unroll
        for (int s = 0; s < 16; s++) {
            unsigned int ah[4];
            ldmatrix4(ah, hbase + (a_row * EK_HSTR + s * 16 + a_col) * 2);
            unsigned int w0, w1;
            unsigned int woff = w2b + ((unsigned)(s * 32 + lane) << 3);
            asm volatile("ld.shared.v2.u32 {%0,%1}, [%2];" : "=r"(w0), "=r"(w1) : "r"(woff));
            mma_f16(cacc, ah, w0, w1);
        }
        __syncwarp();

        long long e0 = eBase + (lane >> 2);
        if (e0 < n_edges) {
            float2 o0 = make_float2(cacc[0] + b2j0, cacc[1] + b2j1);
            *(float2*)(out + e0 * ETYPES + j) = o0;
        }
        if (e0 + 8 < n_edges) {
            float2 o1 = make_float2(cacc[2] + b2j0, cacc[3] + b2j1);
            *(float2*)(out + (e0 + 8) * ETYPES + j) = o1;
        }
        rr = rr_next;
    }
}

// ---------------- launch ----------------
extern "C" void kernel_launch(void* const* d_in, const int* in_sizes, int n_in,
                              void* d_out, int out_size) {
    const float* z  = (const float*)d_in[0];
    const int*   ei = (const int*)d_in[1];
    const float* Wn = (const float*)d_in[2];
    const float* bn = (const float*)d_in[3];
    const float* W1 = (const float*)d_in[4];
    const float* b1 = (const float*)d_in[5];
    const float* W2 = (const float*)d_in[6];
    const float* b2 = (const float*)d_in[7];

    int n_nodes = in_sizes[0] / LATENT;
    int n_edges = in_sizes[1] / 2;
    float* out = (float*)d_out;

    prep_all<<<34, 256>>>(W1, W2);

    int mtiles = (n_nodes + 63) / 64;
    int ntiles = (n_nodes + 31) / 32;
    int n_uv = mtiles * 2;
    cudaFuncSetAttribute(uv_node_kernel, cudaFuncAttributeMaxDynamicSharedMemorySize, UV_SMEM);
    uv_node_kernel<<<n_uv + ntiles, THREADS, UV_SMEM>>>(z, b1, Wn, bn, out, n_nodes, n_uv);

    cudaFuncSetAttribute(edge_kernel, cudaFuncAttributeMaxDynamicSharedMemorySize, EK_SMEM);
    edge_kernel<<<EK_GRID, THREADS, EK_SMEM>>>(ei, b2, out + (size_t)n_nodes * NTYPES,
                                               n_edges, n_nodes);
}

// round 17
// speedup vs baseline: 4.0371x; 1.0522x over previous
#include <cuda_runtime.h>
#include <cuda_fp16.h>
#include <cstdint>

#define LATENT   128
#define HIDDEN   256
#define NTYPES   32
#define ETYPES   8
#define THREADS  256

// ---------- persistent device scratch ----------
// W1 fragment packs, T-pair v4 layout: word idx = ((s*16 + T/2)*32 + lane)*4 + (T&1)*2 + q
__device__ unsigned int g_Bu[16384];
__device__ unsigned int g_Bv[16384];
// W2 fragments (hi only): word idx = (kstep*32 + lane)*2 + q
__device__ unsigned int g_B2[1024];
// UV table: per node 512 fp16 (U' cols 0..255 | V cols 256..511), u32 words
__device__ unsigned int g_UV[12812288];

// ---------- helpers ----------
__device__ __forceinline__ unsigned int smem_u32(const void* p) {
    unsigned int a;
    asm("{ .reg .u64 t; cvta.to.shared.u64 t, %1; cvt.u32.u64 %0, t; }" : "=r"(a) : "l"(p));
    return a;
}
__device__ __forceinline__ unsigned int pack_h2(__half a, __half b) {
    __half2 h = __halves2half2(a, b);
    return *reinterpret_cast<unsigned int*>(&h);
}
__device__ __forceinline__ unsigned int pack_f2(float a, float b) {
    return pack_h2(__float2half_rn(a), __float2half_rn(b));
}
__device__ __forceinline__ unsigned int h2_add_relu(unsigned int a, unsigned int b) {
    __half2 s = __hadd2(*reinterpret_cast<__half2*>(&a), *reinterpret_cast<__half2*>(&b));
    __half2 z = __float2half2_rn(0.f);
    s = __hmax2(s, z);
    return *reinterpret_cast<unsigned int*>(&s);
}
__device__ __forceinline__ void mma_f16(float* c, const unsigned int* a,
                                        unsigned int b0, unsigned int b1) {
    asm volatile(
        "mma.sync.aligned.m16n8k16.row.col.f32.f16.f16.f32 "
        "{%0,%1,%2,%3}, {%4,%5,%6,%7}, {%8,%9}, {%0,%1,%2,%3};"
        : "+f"(c[0]), "+f"(c[1]), "+f"(c[2]), "+f"(c[3])
        : "r"(a[0]), "r"(a[1]), "r"(a[2]), "r"(a[3]), "r"(b0), "r"(b1));
}
__device__ __forceinline__ void ldmatrix4(unsigned int* r, unsigned int addr) {
    asm volatile("ldmatrix.sync.aligned.m8n8.x4.shared.b16 {%0,%1,%2,%3}, [%4];"
                 : "=r"(r[0]), "=r"(r[1]), "=r"(r[2]), "=r"(r[3]) : "r"(addr));
}
__device__ __forceinline__ void cp_async16(unsigned int dst, const void* src) {
    asm volatile("cp.async.cg.shared.global [%0], [%1], 16;" :: "r"(dst), "l"(src));
}
__device__ __forceinline__ void cp_commit() {
    asm volatile("cp.async.commit_group;" ::: "memory");
}
__device__ __forceinline__ void cp_wait0() {
    asm volatile("cp.async.wait_group 0;" ::: "memory");
}

// ---------------- prep: W1 (T-pair v4) + W2 (hi only), one launch ----------
__global__ void prep_all(const float* __restrict__ W1, const float* __restrict__ W2) {
    int b = blockIdx.x;
    int tid = threadIdx.x;
    if (b < 32) {
        int p = b * 256 + tid;                 // (s<8, T<32, l<32)
        int l = p & 31;
        int T = (p >> 5) & 31;
        int s = p >> 10;
        int n  = T * 8 + (l >> 2);
        int kb = s * 16 + 2 * (l & 3);
        int dst = (((s * 16 + (T >> 1)) * 32 + l) << 2) + ((T & 1) * 2);
#pragma unroll
        for (int q = 0; q < 2; q++) {
            int k = kb + q * 8;
            g_Bu[dst + q] = pack_f2(W1[k * HIDDEN + n],         W1[(k + 1) * HIDDEN + n]);
            g_Bv[dst + q] = pack_f2(W1[(k + 128) * HIDDEN + n], W1[(k + 129) * HIDDEN + n]);
        }
    } else {
        int p = (b - 32) * 256 + tid;          // 0..511 (kstep<16, lane<32)
        if (p >= 512) return;
        int lane = p & 31;
        int g   = lane >> 2;
        int tig = lane & 3;
        int k0  = (p >> 5) * 16 + 2 * tig;
#pragma unroll
        for (int q = 0; q < 2; q++) {
            int k = k0 + q * 8;
            g_B2[p * 2 + q] = pack_f2(W2[k * ETYPES + g], W2[(k + 1) * ETYPES + g]);
        }
    }
}

// ---------------- fused uv + node kernel ----------------
// blocks [0, n_uv): UV precompute, one block per 64-node tile (U then V half)
// blocks [n_uv, n_uv + ntiles): node logits (32 nodes per block)
#define UV_ASTR   136
#define UV_SM_B0  (64 * UV_ASTR * 2)          // 17408
#define UV_SMEM   (UV_SM_B0 + 65536)          // 82944
__global__ void __launch_bounds__(THREADS, 2)
uv_node_kernel(const float* __restrict__ z,
               const float* __restrict__ b1,
               const float* __restrict__ Wn,
               const float* __restrict__ bn,
               float* __restrict__ node_out,
               int n_nodes, int n_uv) {
    extern __shared__ char dsm[];
    __shared__ float b1s[HIDDEN];

    int tid  = threadIdx.x;
    int lane = tid & 31;
    int warp = tid >> 5;

    if ((int)blockIdx.x >= n_uv) {
        // ---------------- node-logits branch (smem overlays dynamic region) ----
        float* ws = (float*)dsm;               // 4096 floats
        float* zs = ws + LATENT * NTYPES;      // 32*132
        float* bs = zs + 32 * 132;             // 32
        int nb = blockIdx.x - n_uv;

        for (int idx = tid; idx < LATENT * NTYPES / 4; idx += THREADS)
            ((float4*)ws)[idx] = ((const float4*)Wn)[idx];
        if (tid < NTYPES) bs[tid] = bn[tid];
        long long nBase = (long long)nb * 32;
        for (int idx = tid; idx < 32 * LATENT / 4; idx += THREADS) {
            int n = idx / (LATENT / 4), kk = idx % (LATENT / 4);
            long long gn = nBase + n;
            float4 v = make_float4(0.f, 0.f, 0.f, 0.f);
            if (gn < n_nodes) v = *(const float4*)(z + gn * LATENT + kk * 4);
            *(float4*)(zs + n * 132 + kk * 4) = v;
        }
        __syncthreads();
        int n = tid >> 3, tg = tid & 7;
        float a0 = bs[tg*4+0], a1 = bs[tg*4+1], a2 = bs[tg*4+2], a3 = bs[tg*4+3];
        const float* zr = zs + n * 132;
#pragma unroll 8
        for (int k = 0; k < LATENT; k++) {
            float zv = zr[k];
            float4 w = *(const float4*)(ws + k * NTYPES + tg * 4);
            a0 = fmaf(zv, w.x, a0); a1 = fmaf(zv, w.y, a1);
            a2 = fmaf(zv, w.z, a2); a3 = fmaf(zv, w.w, a3);
        }
        long long gn = nBase + n;
        if (gn < n_nodes)
            *(float4*)(node_out + gn * NTYPES + tg * 4) = make_float4(a0, a1, a2, a3);
        return;
    }

    // ---------------- UV branch: one block does U then V for 64 nodes ----------
    int mh   = warp >> 2;
    int nq   = warp & 3;
    long long nodeBase = (long long)blockIdx.x * 64;

    unsigned int smb = smem_u32(dsm);
    unsigned int bbase = smb + UV_SM_B0;

    // prefetch B_u (64 KB)
    {
        const uint4* sb = (const uint4*)g_Bu;
#pragma unroll
        for (int u = 0; u < 16; u++)
            cp_async16(bbase + (tid + u * THREADS) * 16, sb + tid + u * THREADS);
        cp_commit();
    }

    if (tid < HIDDEN) b1s[tid] = b1[tid];

    // stage A: 64 nodes x 128 k fp16 (done ONCE, reused for U and V)
    {
        int n_l = tid >> 2;
        int q   = tid & 3;
        long long node = nodeBase + n_l;
        if (node >= n_nodes) node = n_nodes - 1;
        const float* src = z + node * LATENT + q * 32;
        unsigned short* A = (unsigned short*)dsm;
        int base = n_l * UV_ASTR + q * 32;
#pragma unroll
        for (int gg = 0; gg < 4; gg++) {
            float4 a = *(const float4*)(src + gg * 8);
            float4 b = *(const float4*)(src + gg * 8 + 4);
            uint4 pk;
            pk.x = pack_f2(a.x, a.y);
            pk.y = pack_f2(a.z, a.w);
            pk.z = pack_f2(b.x, b.y);
            pk.w = pack_f2(b.z, b.w);
            *(uint4*)(A + base + gg * 8) = pk;
        }
    }

    unsigned int a_row = (unsigned)(lane & 15);
    unsigned int a_col = (unsigned)((lane >> 4) * 8);
    int g   = lane >> 2;
    int tig = lane & 3;

    for (int p = 0; p < 2; p++) {
        cp_wait0();
        __syncthreads();

        float acc[2][8][4];
#pragma unroll
        for (int i = 0; i < 2; i++)
#pragma unroll
            for (int t = 0; t < 8; t++)
#pragma unroll
                for (int r = 0; r < 4; r++) acc[i][t][r] = 0.f;

#pragma unroll
        for (int s = 0; s < 8; s++) {
            int k0 = s * 16;
            unsigned int bw[8][2];
#pragma unroll
            for (int tt = 0; tt < 4; tt++) {
                unsigned int boff = bbase + (((unsigned)(s * 16 + nq * 4 + tt) * 32 + lane) << 4);
                uint4 v;
                asm volatile("ld.shared.v4.u32 {%0,%1,%2,%3}, [%4];"
                             : "=r"(v.x), "=r"(v.y), "=r"(v.z), "=r"(v.w) : "r"(boff));
                bw[2 * tt][0]     = v.x; bw[2 * tt][1]     = v.y;
                bw[2 * tt + 1][0] = v.z; bw[2 * tt + 1][1] = v.w;
            }
#pragma unroll
            for (int i = 0; i < 2; i++) {
                unsigned int ah[4];
                int mrow = (mh * 2 + i) * 16;
                unsigned int off = ((mrow + a_row) * UV_ASTR + k0 + a_col) * 2;
                ldmatrix4(ah, smb + off);
#pragma unroll
                for (int t = 0; t < 8; t++)
                    mma_f16(acc[i][t], ah, bw[t][0], bw[t][1]);
            }
        }

        // before overwriting B buffer: all warps must be done reading it
        if (p == 0) {
            __syncthreads();
            const uint4* sb = (const uint4*)g_Bv;
#pragma unroll
            for (int u = 0; u < 16; u++)
                cp_async16(bbase + (tid + u * THREADS) * 16, sb + tid + u * THREADS);
            cp_commit();
        }

        // epilogue (+b1 only for U-half); overlaps with B_v cp.async when p==0
#pragma unroll
        for (int i = 0; i < 2; i++) {
#pragma unroll
            for (int t = 0; t < 8; t++) {
                int col = nq * 64 + t * 8 + 2 * tig;
                float bb0 = p ? 0.f : b1s[col];
                float bb1 = p ? 0.f : b1s[col + 1];
                long long node0 = nodeBase + (mh * 2 + i) * 16 + g;
                unsigned int h20 = pack_f2(acc[i][t][0] + bb0, acc[i][t][1] + bb1);
                unsigned int h21 = pack_f2(acc[i][t][2] + bb0, acc[i][t][3] + bb1);
                if (node0 < n_nodes)
                    g_UV[node0 * 256 + p * 128 + (col >> 1)] = h20;
                if (node0 + 8 < n_nodes)
                    g_UV[(node0 + 8) * 256 + p * 128 + (col >> 1)] = h21;
            }
        }
    }
}

// ---------------- edge kernel: W2 hi-only in smem, 3 CTAs/SM, balanced grid ----
#define EK_HSTR  264
#define EK_WBUF  (16 * EK_HSTR * 2)           // 8448
#define EK_W2OFF (8 * EK_WBUF)                // 67584
#define EK_SMEM  (EK_W2OFF + 4096)            // 71680
#define EK_GRID  3125                          // 25000 warp-slots -> exactly 2 groups/warp
__global__ void __launch_bounds__(THREADS, 3)
edge_kernel(const int* __restrict__ ei,
            const float* __restrict__ b2,
            float* __restrict__ out,
            int n_edges, int n_nodes) {
    extern __shared__ char dsm[];
    int tid  = threadIdx.x;
    int lane = tid & 31;
    int warp = tid >> 5;

    unsigned int smb   = smem_u32(dsm);
    unsigned int hbase = smb + warp * EK_WBUF;
    unsigned int w2b   = smb + EK_W2OFF;

    // stage W2 fragments (hi) into smem: 1024 words
    {
        unsigned int* w2s = (unsigned int*)(dsm + EK_W2OFF);
#pragma unroll
        for (int u = 0; u < 4; u++)
            w2s[tid + u * THREADS] = g_B2[tid + u * THREADS];
    }
    __syncthreads();

    int j = 2 * (lane & 3);
    float b2j0 = b2[j], b2j1 = b2[j + 1];

    unsigned int a_row = (unsigned)(lane & 15);
    unsigned int a_col = (unsigned)((lane >> 4) * 8);

    int n_groups = (n_edges + 15) >> 4;
    int stride = EK_GRID * 8;
    int grp = blockIdx.x * 8 + warp;
    if (grp >= n_groups) return;

    // preload first group's indices
    long long my_e = (long long)grp * 16 + (lane & 15);
    if (my_e >= n_edges) my_e = n_edges - 1;
    int rr = (lane < 16) ? ei[my_e] : ei[(long long)n_edges + my_e];
    rr = min(max(rr, 0), n_nodes - 1);

    for (; grp < n_groups; grp += stride) {
        long long eBase = (long long)grp * 16;

        // gather + h = relu(U' + V)
#pragma unroll
        for (int g = 0; g < 16; g++) {
            int r = __shfl_sync(0xffffffffu, rr, g);
            int c = __shfl_sync(0xffffffffu, rr, 16 + g);
            uint4 u = *(const uint4*)(g_UV + (long long)r * 256 + lane * 4);
            uint4 v = *(const uint4*)(g_UV + (long long)c * 256 + 128 + lane * 4);
            uint4 h;
            h.x = h2_add_relu(u.x, v.x);
            h.y = h2_add_relu(u.y, v.y);
            h.z = h2_add_relu(u.z, v.z);
            h.w = h2_add_relu(u.w, v.w);
            asm volatile("st.shared.v4.b32 [%0], {%1,%2,%3,%4};"
                         :: "r"(hbase + (unsigned)(g * EK_HSTR + lane * 8) * 2),
                            "r"(h.x), "r"(h.y), "r"(h.z), "r"(h.w) : "memory");
        }

        // prefetch next group's indices (overlaps with GEMM2)
        int rr_next = rr;
        if (grp + stride < n_groups) {
            long long ne = (long long)(grp + stride) * 16 + (lane & 15);
            if (ne >= n_edges) ne = n_edges - 1;
            rr_next = (lane < 16) ? ei[ne] : ei[(long long)n_edges + ne];
            rr_next = min(max(rr_next, 0), n_nodes - 1);
        }
        __syncwarp();

        // GEMM2: 16 k-steps, one v2 W2 load + one MMA per step
        float cacc[4] = {0.f, 0.f, 0.f, 0.f};
#pragma unroll
        for (int s = 0; s < 16; s++) {
            unsigned int ah[4];
            ldmatrix4(ah, hbase + (a_row * EK_HSTR + s * 16 + a_col) * 2);
            unsigned int w0, w1;
            unsigned int woff = w2b + ((unsigned)(s * 32 + lane) << 3);
            asm volatile("ld.shared.v2.u32 {%0,%1}, [%2];" : "=r"(w0), "=r"(w1) : "r"(woff));
            mma_f16(cacc, ah, w0, w1);
        }
        __syncwarp();

        long long e0 = eBase + (lane >> 2);
        if (e0 < n_edges) {
            float2 o0 = make_float2(cacc[0] + b2j0, cacc[1] + b2j1);
            *(float2*)(out + e0 * ETYPES + j) = o0;
        }
        if (e0 + 8 < n_edges) {
            float2 o1 = make_float2(cacc[2] + b2j0, cacc[3] + b2j1);
            *(float2*)(out + (e0 + 8) * ETYPES + j) = o1;
        }
        rr = rr_next;
    }
}

// ---------------- launch ----------------
extern "C" void kernel_launch(void* const* d_in, const int* in_sizes, int n_in,
                              void* d_out, int out_size) {
    const float* z  = (const float*)d_in[0];
    const int*   ei = (const int*)d_in[1];
    const float* Wn = (const float*)d_in[2];
    const float* bn = (const float*)d_in[3];
    const float* W1 = (const float*)d_in[4];
    const float* b1 = (const float*)d_in[5];
    const float* W2 = (const float*)d_in[6];
    const float* b2 = (const float*)d_in[7];

    int n_nodes = in_sizes[0] / LATENT;
    int n_edges = in_sizes[1] / 2;
    float* out = (float*)d_out;

    prep_all<<<34, 256>>>(W1, W2);

    int mtiles = (n_nodes + 63) / 64;
    int ntiles = (n_nodes + 31) / 32;
    cudaFuncSetAttribute(uv_node_kernel, cudaFuncAttributeMaxDynamicSharedMemorySize, UV_SMEM);
    uv_node_kernel<<<mtiles + ntiles, THREADS, UV_SMEM>>>(z, b1, Wn, bn, out, n_nodes, mtiles);

    cudaFuncSetAttribute(edge_kernel, cudaFuncAttributeMaxDynamicSharedMemorySize, EK_SMEM);
    edge_kernel<<<EK_GRID, THREADS, EK_SMEM>>>(ei, b2, out + (size_t)n_nodes * NTYPES,
                                               n_edges, n_nodes);
}